// round 9
// baseline (speedup 1.0000x reference)
#include <cuda_runtime.h>
#include <cuda_bf16.h>
#include <stdint.h>
#include <math.h>

#define NN 4096
#define HH 256
#define EE 65536
#define SPLITS 8

// ---------------- device scratch ----------------
__device__ float g_h[NN * HH];
__device__ float g_xlin[NN * HH];
__device__ float g_qkv[NN * 3 * HH];
__device__ float g_attn[NN * HH];
__device__ float g_proj[NN * HH];
__device__ float g_agg[NN * HH];
__device__ float g_out[NN * HH];
__device__ float g_ffn[NN * 2 * HH];
__device__ float g_hid[NN * HH];
__device__ float g_deg[NN];
__device__ float g_dinv[NN];
__device__ float g_opart[SPLITS * NN * HH];
__device__ float g_mpart[SPLITS * 4 * NN];
__device__ float g_lpart[SPLITS * 4 * NN];

// tf32-bit weight/x pool
#define OFF_X      0
#define OFF_PREW   524288
#define OFF_LBASE  557056
#define LSTRIDE    589824
#define LOFF_GCN   0
#define LOFF_INW   65536
#define LOFF_OUTW  262144
#define LOFF_FFN1  327680
#define LOFF_FFN2  458752
#define OFF_MLP1   1736704
#define OFF_MLP2   1802240
#define WPOOL_TOTAL 2850816
__device__ float g_wpool[WPOOL_TOTAL];

// ---------------- helpers ----------------
__device__ __forceinline__ uint32_t f2tf(float f) {
    uint32_t u;
    asm("cvt.rna.tf32.f32 %0, %1;" : "=r"(u) : "f"(f));
    return u;
}

__device__ __forceinline__ void mma_tf32(float c[4], const uint32_t a[4], const uint32_t b[2]) {
    asm volatile(
        "mma.sync.aligned.m16n8k8.row.col.f32.tf32.tf32.f32 "
        "{%0,%1,%2,%3},{%4,%5,%6,%7},{%8,%9},{%0,%1,%2,%3};\n"
        : "+f"(c[0]), "+f"(c[1]), "+f"(c[2]), "+f"(c[3])
        : "r"(a[0]), "r"(a[1]), "r"(a[2]), "r"(a[3]), "r"(b[0]), "r"(b[1]));
}

__device__ __forceinline__ void cpa16(void* s, const void* g) {
    uint32_t sa = (uint32_t)__cvta_generic_to_shared(s);
    asm volatile("cp.async.cg.shared.global [%0], [%1], 16;\n" :: "r"(sa), "l"(g) : "memory");
}
#define CP_COMMIT asm volatile("cp.async.commit_group;\n" ::: "memory")
template<int W> __device__ __forceinline__ void cp_wait() {
    asm volatile("cp.async.wait_group %0;\n" :: "n"(W) : "memory");
}

// ---------------- batched tf32 conversion of weights + x ----------------
struct ConvBatch {
    const float* src[14];
    float* dst[14];
    int n[14];
};

__global__ void conv_tf32_batch(ConvBatch b) {
    int t = blockIdx.y;
    int n = b.n[t];
    const float* s = b.src[t];
    float* d = b.dst[t];
    for (int i = blockIdx.x * blockDim.x + threadIdx.x; i < n; i += gridDim.x * blockDim.x)
        d[i] = __uint_as_float(f2tf(s[i]));
}

// ---------------- TF32 GEMM: operands are tf32 BIT PATTERNS; no cvt in hot loop ----------------
// C = act(A @ W^T + bias + add). outmode: 0 = fp32, 1 = tf32 bits, 2 = qkv (bits, cols<HH *0.125)
#define GBK 16

__global__ void __launch_bounds__(128) tgemm(
    const float* __restrict__ A, const float* __restrict__ W,
    const float* __restrict__ bias, const float* __restrict__ add,
    float* __restrict__ C, int M, int Nn, int K, int relu, int outmode) {
    __shared__ float As[3][64][20];
    __shared__ float Ws[3][64][20];

    int tid = threadIdx.x;
    int lane = tid & 31, wid = tid >> 5;
    int warp_m = wid & 1, warp_n = wid >> 1;
    int m0 = blockIdx.y * 64, n0 = blockIdx.x * 64;

    float c[2][4][4];
#pragma unroll
    for (int mt = 0; mt < 2; mt++)
#pragma unroll
        for (int nt = 0; nt < 4; nt++)
#pragma unroll
            for (int r = 0; r < 4; r++) c[mt][nt][r] = 0.f;

    int nIter = K / GBK;

    auto issue = [&](int it, int buf) {
        int k0 = it * GBK;
#pragma unroll
        for (int j = 0; j < 2; j++) {
            int cc = tid + 128 * j;
            int row = cc >> 2, ch = (cc & 3) * 4;
            cpa16(&As[buf][row][ch], &A[(long)(m0 + row) * K + k0 + ch]);
            cpa16(&Ws[buf][row][ch], &W[(long)(n0 + row) * K + k0 + ch]);
        }
    };

    issue(0, 0); CP_COMMIT;
    issue(1, 1); CP_COMMIT;

    for (int i = 0; i < nIter; i++) {
        int buf = i % 3;
        if (i + 2 < nIter) { issue(i + 2, (i + 2) % 3); CP_COMMIT; cp_wait<2>(); }
        else if (i + 1 < nIter) cp_wait<1>();
        else cp_wait<0>();
        __syncthreads();

#pragma unroll
        for (int ks = 0; ks < GBK; ks += 8) {
            uint32_t a[2][4], b[4][2];
            int kk = ks + (lane & 3);
#pragma unroll
            for (int mt = 0; mt < 2; mt++) {
                int row = warp_m * 32 + mt * 16 + (lane >> 2);
                a[mt][0] = __float_as_uint(As[buf][row][kk]);
                a[mt][1] = __float_as_uint(As[buf][row + 8][kk]);
                a[mt][2] = __float_as_uint(As[buf][row][kk + 4]);
                a[mt][3] = __float_as_uint(As[buf][row + 8][kk + 4]);
            }
#pragma unroll
            for (int nt = 0; nt < 4; nt++) {
                int nc = warp_n * 32 + nt * 8 + (lane >> 2);
                b[nt][0] = __float_as_uint(Ws[buf][nc][kk]);
                b[nt][1] = __float_as_uint(Ws[buf][nc][kk + 4]);
            }
#pragma unroll
            for (int mt = 0; mt < 2; mt++)
#pragma unroll
                for (int nt = 0; nt < 4; nt++) mma_tf32(c[mt][nt], a[mt], b[nt]);
        }
        __syncthreads();
    }

    // epilogue
#pragma unroll
    for (int mt = 0; mt < 2; mt++) {
        int rb = m0 + warp_m * 32 + mt * 16 + (lane >> 2);
#pragma unroll
        for (int nt = 0; nt < 4; nt++) {
            int cb = n0 + warp_n * 32 + nt * 8 + 2 * (lane & 3);
#pragma unroll
            for (int r = 0; r < 4; r++) {
                int mm = rb + (r >> 1) * 8;
                int nn = cb + (r & 1);
                float v = c[mt][nt][r];
                if (bias) v += bias[nn];
                if (add)  v += add[(long)mm * Nn + nn];
                if (relu) v = fmaxf(v, 0.f);
                if (outmode == 0) {
                    C[(long)mm * Nn + nn] = v;
                } else {
                    if (outmode == 2 && nn < HH) v *= 0.125f;
                    C[(long)mm * Nn + nn] = __uint_as_float(f2tf(v));
                }
            }
        }
    }
}

// ---------------- TF32 flash attention (qkv holds tf32 bits, Q pre-scaled) ----------------
#define KST 68
#define VST 72
#define KBUF (64 * KST)
#define VBUF (64 * VST)

__global__ void __launch_bounds__(128) flash_part(const float* __restrict__ qkv,
                                                  float* __restrict__ opart,
                                                  float* __restrict__ mpart,
                                                  float* __restrict__ lpart) {
    extern __shared__ float sm[];
    float* Ks = sm;                 // [2][64][KST]; reused as P after S-matmul
    float* Vs = sm + 2 * KBUF;      // [2][64][VST]

    int tid = threadIdx.x;
    int lane = tid & 31, wid = tid >> 5;
    int q0 = blockIdx.x * 64;
    int head = blockIdx.y;
    int split = blockIdx.z;
    const int C3 = 3 * HH;
    const int qoff = head * 64, koff = HH + head * 64, voff = 2 * HH + head * 64;

    uint32_t qa[8][4];
    {
        int r = q0 + wid * 16 + (lane >> 2);
#pragma unroll
        for (int kt = 0; kt < 8; kt++) {
            int d = kt * 8 + (lane & 3);
            qa[kt][0] = __float_as_uint(qkv[(long)r * C3 + qoff + d]);
            qa[kt][1] = __float_as_uint(qkv[(long)(r + 8) * C3 + qoff + d]);
            qa[kt][2] = __float_as_uint(qkv[(long)r * C3 + qoff + d + 4]);
            qa[kt][3] = __float_as_uint(qkv[(long)(r + 8) * C3 + qoff + d + 4]);
        }
    }

    float m0 = -1e30f, m1 = -1e30f, l0 = 0.f, l1 = 0.f;
    float o[8][4];
#pragma unroll
    for (int nt = 0; nt < 8; nt++)
#pragma unroll
        for (int r = 0; r < 4; r++) o[nt][r] = 0.f;

    int kbase = split * (NN / SPLITS);
    const int nIter = (NN / SPLITS) / 64;

    auto issue = [&](int it, int buf) {
        int k0 = kbase + it * 64;
#pragma unroll
        for (int j = 0; j < 8; j++) {
            int cc = tid + 128 * j;
            int key = cc >> 4, ch = (cc & 15) * 4;
            cpa16(&Ks[buf * KBUF + key * KST + ch], &qkv[(long)(k0 + key) * C3 + koff + ch]);
            cpa16(&Vs[buf * VBUF + key * VST + ch], &qkv[(long)(k0 + key) * C3 + voff + ch]);
        }
    };

    issue(0, 0); CP_COMMIT;
    int cur = 0;
    for (int i = 0; i < nIter; i++) {
        if (i + 1 < nIter) { issue(i + 1, cur ^ 1); CP_COMMIT; cp_wait<1>(); }
        else cp_wait<0>();
        __syncthreads();

        float* Kc = Ks + cur * KBUF;
        const float* Vc = Vs + cur * VBUF;

        float s[8][4];
#pragma unroll
        for (int nt = 0; nt < 8; nt++)
#pragma unroll
            for (int r = 0; r < 4; r++) s[nt][r] = 0.f;
#pragma unroll
        for (int kt = 0; kt < 8; kt++) {
            int kk = kt * 8 + (lane & 3);
            uint32_t b[2];
#pragma unroll
            for (int nt = 0; nt < 8; nt++) {
                int key = nt * 8 + (lane >> 2);
                b[0] = __float_as_uint(Kc[key * KST + kk]);
                b[1] = __float_as_uint(Kc[key * KST + kk + 4]);
                mma_tf32(s[nt], qa[kt], b);
            }
        }

        float mx0 = -1e30f, mx1 = -1e30f;
#pragma unroll
        for (int nt = 0; nt < 8; nt++) {
            mx0 = fmaxf(mx0, fmaxf(s[nt][0], s[nt][1]));
            mx1 = fmaxf(mx1, fmaxf(s[nt][2], s[nt][3]));
        }
#pragma unroll
        for (int off = 1; off <= 2; off <<= 1) {
            mx0 = fmaxf(mx0, __shfl_xor_sync(0xffffffffu, mx0, off));
            mx1 = fmaxf(mx1, __shfl_xor_sync(0xffffffffu, mx1, off));
        }
        float mn0 = fmaxf(m0, mx0), mn1 = fmaxf(m1, mx1);
        float sum0 = 0.f, sum1 = 0.f;
#pragma unroll
        for (int nt = 0; nt < 8; nt++) {
            s[nt][0] = __expf(s[nt][0] - mn0);
            s[nt][1] = __expf(s[nt][1] - mn0);
            s[nt][2] = __expf(s[nt][2] - mn1);
            s[nt][3] = __expf(s[nt][3] - mn1);
            sum0 += s[nt][0] + s[nt][1];
            sum1 += s[nt][2] + s[nt][3];
        }
#pragma unroll
        for (int off = 1; off <= 2; off <<= 1) {
            sum0 += __shfl_xor_sync(0xffffffffu, sum0, off);
            sum1 += __shfl_xor_sync(0xffffffffu, sum1, off);
        }
        float e0 = __expf(m0 - mn0), e1 = __expf(m1 - mn1);
        l0 = l0 * e0 + sum0;
        l1 = l1 * e1 + sum1;
        m0 = mn0; m1 = mn1;
#pragma unroll
        for (int nt = 0; nt < 8; nt++) {
            o[nt][0] *= e0; o[nt][1] *= e0;
            o[nt][2] *= e1; o[nt][3] *= e1;
        }

        __syncthreads();

        {
            int r = wid * 16 + (lane >> 2);
#pragma unroll
            for (int nt = 0; nt < 8; nt++) {
                int cb = nt * 8 + 2 * (lane & 3);
                Kc[r * KST + cb]           = __uint_as_float(f2tf(s[nt][0]));
                Kc[r * KST + cb + 1]       = __uint_as_float(f2tf(s[nt][1]));
                Kc[(r + 8) * KST + cb]     = __uint_as_float(f2tf(s[nt][2]));
                Kc[(r + 8) * KST + cb + 1] = __uint_as_float(f2tf(s[nt][3]));
            }
        }
        __syncwarp();

#pragma unroll
        for (int kt = 0; kt < 8; kt++) {
            int r = wid * 16 + (lane >> 2);
            int kk = kt * 8 + (lane & 3);
            uint32_t a[4];
            a[0] = __float_as_uint(Kc[r * KST + kk]);
            a[1] = __float_as_uint(Kc[(r + 8) * KST + kk]);
            a[2] = __float_as_uint(Kc[r * KST + kk + 4]);
            a[3] = __float_as_uint(Kc[(r + 8) * KST + kk + 4]);
            uint32_t b[2];
#pragma unroll
            for (int nt = 0; nt < 8; nt++) {
                int dd = nt * 8 + (lane >> 2);
                b[0] = __float_as_uint(Vc[kk * VST + dd]);
                b[1] = __float_as_uint(Vc[(kk + 4) * VST + dd]);
                mma_tf32(o[nt], a, b);
            }
        }
        __syncthreads();
        cur ^= 1;
    }

    int r = q0 + wid * 16 + (lane >> 2);
    float* ob = opart + (long)split * NN * HH;
#pragma unroll
    for (int nt = 0; nt < 8; nt++) {
        int cb = head * 64 + nt * 8 + 2 * (lane & 3);
        ob[(long)r * HH + cb]           = o[nt][0];
        ob[(long)r * HH + cb + 1]       = o[nt][1];
        ob[(long)(r + 8) * HH + cb]     = o[nt][2];
        ob[(long)(r + 8) * HH + cb + 1] = o[nt][3];
    }
    if ((lane & 3) == 0) {
        int base = (split * 4 + head) * NN;
        mpart[base + r] = m0;     lpart[base + r] = l0;
        mpart[base + r + 8] = m1; lpart[base + r + 8] = l1;
    }
}

// merge -> attn stored as tf32 bits (attn is a GEMM-A operand)
__global__ void flash_merge(const float* __restrict__ opart, const float* __restrict__ mpart,
                            const float* __restrict__ lpart, float* __restrict__ out) {
    int idx = blockIdx.x * blockDim.x + threadIdx.x;
    if (idx >= NN * HH) return;
    int row = idx >> 8, c = idx & 255, head = c >> 6;
    float mv[SPLITS], lv[SPLITS];
    float mmax = -1e30f;
#pragma unroll
    for (int s = 0; s < SPLITS; s++) {
        mv[s] = mpart[(s * 4 + head) * NN + row];
        lv[s] = lpart[(s * 4 + head) * NN + row];
        mmax = fmaxf(mmax, mv[s]);
    }
    float num = 0.f, den = 0.f;
#pragma unroll
    for (int s = 0; s < SPLITS; s++) {
        float w = __expf(mv[s] - mmax);
        num += opart[(long)s * NN * HH + idx] * w;
        den += lv[s] * w;
    }
    out[idx] = __uint_as_float(f2tf(num / den));
}

// ---------------- GCN helpers ----------------
__global__ void deg_init(float* deg, int n) {
    int i = blockIdx.x * blockDim.x + threadIdx.x;
    if (i < n) deg[i] = 1.f;
}
__global__ void deg_count(const int* __restrict__ dst, float* deg, int e) {
    int i = blockIdx.x * blockDim.x + threadIdx.x;
    if (i < e) atomicAdd(&deg[dst[i]], 1.f);
}
__global__ void dinv_kernel(const float* __restrict__ deg, float* dinv, int n) {
    int i = blockIdx.x * blockDim.x + threadIdx.x;
    if (i < n) dinv[i] = rsqrtf(deg[i]);
}

__global__ void gcn_scatter(const int* __restrict__ src, const int* __restrict__ dst,
                            const float* __restrict__ dinv, const float* __restrict__ xlin,
                            float* __restrict__ agg, int e) {
    int w = (blockIdx.x * blockDim.x + threadIdx.x) >> 5;
    int lane = threadIdx.x & 31;
    if (w >= e) return;
    int s = src[w], d = dst[w];
    float coef = dinv[s] * dinv[d];
    const float* xs = xlin + (long)s * HH;
    float* ad = agg + (long)d * HH;
#pragma unroll
    for (int k = 0; k < HH / 32; k++)
        atomicAdd(&ad[lane + 32 * k], xs[lane + 32 * k] * coef);
}

// outb stored as tf32 bits (GEMM-A operand of ffn1, add-operand of ffn2)
__global__ void combine(const float* __restrict__ agg, const float* __restrict__ xlin,
                        const float* __restrict__ dinv, const float* __restrict__ gcn_b,
                        const float* __restrict__ proj, const float* __restrict__ h,
                        float* __restrict__ out, int total) {
    int idx = blockIdx.x * blockDim.x + threadIdx.x;
    if (idx >= total) return;
    int i = idx >> 8, c = idx & 255;
    float dv = dinv[i];
    float v = agg[idx] + xlin[idx] * dv * dv + gcn_b[c] + proj[idx] + 2.f * h[idx];
    out[idx] = __uint_as_float(f2tf(v));
}

// ---------------- tiled symmetrize ----------------
__global__ void __launch_bounds__(256) symmetrize(float* __restrict__ o) {
    int ti = blockIdx.y, tj = blockIdx.x;
    if (tj < ti) return;
    __shared__ float As[64][65];
    __shared__ float Bs[64][65];
    int tid = threadIdx.x;
    int r = tid >> 2, c0 = (tid & 3) * 16;
    long base_a = (long)ti * 64 * NN + tj * 64;
    long base_b = (long)tj * 64 * NN + ti * 64;

#pragma unroll
    for (int j = 0; j < 16; j += 4) {
        float4 va = *(const float4*)&o[base_a + (long)r * NN + c0 + j];
        float4 vb = *(const float4*)&o[base_b + (long)r * NN + c0 + j];
        As[r][c0 + j] = va.x; As[r][c0 + j + 1] = va.y;
        As[r][c0 + j + 2] = va.z; As[r][c0 + j + 3] = va.w;
        Bs[r][c0 + j] = vb.x; Bs[r][c0 + j + 1] = vb.y;
        Bs[r][c0 + j + 2] = vb.z; Bs[r][c0 + j + 3] = vb.w;
    }
    __syncthreads();

#pragma unroll
    for (int j = 0; j < 16; j += 4) {
        float4 wa, wb;
        wa.x = 0.5f * (As[r][c0 + j]     + Bs[c0 + j][r]);
        wa.y = 0.5f * (As[r][c0 + j + 1] + Bs[c0 + j + 1][r]);
        wa.z = 0.5f * (As[r][c0 + j + 2] + Bs[c0 + j + 2][r]);
        wa.w = 0.5f * (As[r][c0 + j + 3] + Bs[c0 + j + 3][r]);
        *(float4*)&o[base_a + (long)r * NN + c0 + j] = wa;
        if (ti != tj) {
            wb.x = 0.5f * (Bs[r][c0 + j]     + As[c0 + j][r]);
            wb.y = 0.5f * (Bs[r][c0 + j + 1] + As[c0 + j + 1][r]);
            wb.z = 0.5f * (Bs[r][c0 + j + 2] + As[c0 + j + 2][r]);
            wb.w = 0.5f * (Bs[r][c0 + j + 3] + As[c0 + j + 3][r]);
            *(float4*)&o[base_b + (long)r * NN + c0 + j] = wb;
        }
    }
}

// ---------------- launch ----------------
extern "C" void kernel_launch(void* const* d_in, const int* in_sizes, int n_in,
                              void* d_out, int out_size) {
    const float* x      = (const float*)d_in[0];
    const int*   ei     = (const int*)d_in[1];
    const float* pre_b  = (const float*)d_in[3];
    const float* mlp_b1 = (const float*)d_in[25];
    const float* mlp_b2 = (const float*)d_in[27];

    float *h, *xlin, *qkv, *attn, *proj, *agg, *outb, *ffn, *hid, *deg, *dinv;
    float *opart, *mpart, *lpart, *wpool;
    cudaGetSymbolAddress((void**)&h,    g_h);
    cudaGetSymbolAddress((void**)&xlin, g_xlin);
    cudaGetSymbolAddress((void**)&qkv,  g_qkv);
    cudaGetSymbolAddress((void**)&attn, g_attn);
    cudaGetSymbolAddress((void**)&proj, g_proj);
    cudaGetSymbolAddress((void**)&agg,  g_agg);
    cudaGetSymbolAddress((void**)&outb, g_out);
    cudaGetSymbolAddress((void**)&ffn,  g_ffn);
    cudaGetSymbolAddress((void**)&hid,  g_hid);
    cudaGetSymbolAddress((void**)&deg,  g_deg);
    cudaGetSymbolAddress((void**)&dinv, g_dinv);
    cudaGetSymbolAddress((void**)&opart, g_opart);
    cudaGetSymbolAddress((void**)&mpart, g_mpart);
    cudaGetSymbolAddress((void**)&lpart, g_lpart);
    cudaGetSymbolAddress((void**)&wpool, g_wpool);

    const int flash_smem = (2 * KBUF + 2 * VBUF) * (int)sizeof(float);  // 71680
    cudaFuncSetAttribute(flash_part, cudaFuncAttributeMaxDynamicSharedMemorySize, flash_smem);

    // --- batched tf32 conversion of x + all weights ---
    ConvBatch cb;
    int ci = 0;
    auto addc = [&](const float* s, long off, int n) {
        cb.src[ci] = s; cb.dst[ci] = wpool + off; cb.n[ci] = n; ci++;
    };
    addc(x, OFF_X, NN * 128);
    addc((const float*)d_in[2], OFF_PREW, HH * 128);
    for (int L = 0; L < 2; L++) {
        int base = 4 + L * 10;
        long lb = OFF_LBASE + (long)L * LSTRIDE;
        addc((const float*)d_in[base + 0], lb + LOFF_GCN,  HH * HH);
        addc((const float*)d_in[base + 2], lb + LOFF_INW,  3 * HH * HH);
        addc((const float*)d_in[base + 4], lb + LOFF_OUTW, HH * HH);
        addc((const float*)d_in[base + 6], lb + LOFF_FFN1, 2 * HH * HH);
        addc((const float*)d_in[base + 8], lb + LOFF_FFN2, 2 * HH * HH);
    }
    addc((const float*)d_in[24], OFF_MLP1, HH * HH);
    addc((const float*)d_in[26], OFF_MLP2, NN * HH);
    conv_tf32_batch<<<dim3(64, 14), 256>>>(cb);

    deg_init<<<(NN + 255) / 256, 256>>>(deg, NN);
    deg_count<<<(EE + 255) / 256, 256>>>(ei + EE, deg, EE);
    dinv_kernel<<<(NN + 255) / 256, 256>>>(deg, dinv, NN);

    // pre: h = relu(xc @ pre_wc^T + pre_b)   (bits out)
    tgemm<<<dim3(HH / 64, NN / 64), 128>>>(wpool + OFF_X, wpool + OFF_PREW, pre_b, nullptr,
                                           h, NN, HH, 128, 1, 1);

    for (int L = 0; L < 2; L++) {
        int base = 4 + L * 10;
        long lb = OFF_LBASE + (long)L * LSTRIDE;
        const float* gcn_b  = (const float*)d_in[base + 1];
        const float* in_b   = (const float*)d_in[base + 3];
        const float* out_b  = (const float*)d_in[base + 5];
        const float* ffn_b1 = (const float*)d_in[base + 7];
        const float* ffn_b2 = (const float*)d_in[base + 9];

        // xlin: fp32 out (consumed by scatter/combine only)
        tgemm<<<dim3(HH / 64, NN / 64), 128>>>(h, wpool + lb + LOFF_GCN, nullptr, nullptr,
                                               xlin, NN, HH, HH, 0, 0);
        // qkv: bits out, Q pre-scaled
        tgemm<<<dim3(3 * HH / 64, NN / 64), 128>>>(h, wpool + lb + LOFF_INW, in_b, nullptr,
                                                   qkv, NN, 3 * HH, HH, 0, 2);
        flash_part<<<dim3(NN / 64, 4, SPLITS), 128, flash_smem>>>(qkv, opart, mpart, lpart);
        flash_merge<<<(NN * HH) / 256, 256>>>(opart, mpart, lpart, attn);
        // proj: fp32 out (consumed by combine only)
        tgemm<<<dim3(HH / 64, NN / 64), 128>>>(attn, wpool + lb + LOFF_OUTW, out_b, nullptr,
                                               proj, NN, HH, HH, 0, 0);
        cudaMemsetAsync(agg, 0, (size_t)NN * HH * sizeof(float));
        gcn_scatter<<<(EE * 32) / 256, 256>>>(ei, ei + EE, dinv, xlin, agg, EE);
        combine<<<(NN * HH) / 256, 256>>>(agg, xlin, dinv, gcn_b, proj, h, outb, NN * HH);
        // ffn1: bits out
        tgemm<<<dim3(2 * HH / 64, NN / 64), 128>>>(outb, wpool + lb + LOFF_FFN1, ffn_b1, nullptr,
                                                   ffn, NN, 2 * HH, HH, 1, 1);
        // h = relu(outb + ffn @ w2^T + b2): bits out
        tgemm<<<dim3(HH / 64, NN / 64), 128>>>(ffn, wpool + lb + LOFF_FFN2, ffn_b2, outb,
                                               h, NN, HH, 2 * HH, 1, 1);
    }

    // head
    tgemm<<<dim3(HH / 64, NN / 64), 128>>>(h, wpool + OFF_MLP1, mlp_b1, nullptr,
                                           hid, NN, HH, HH, 1, 1);
    tgemm<<<dim3(NN / 64, NN / 64), 128>>>(hid, wpool + OFF_MLP2, mlp_b2, nullptr,
                                           (float*)d_out, NN, NN, HH, 0, 0);
    symmetrize<<<dim3(NN / 64, NN / 64), 256>>>((float*)d_out);
}

// round 10
// speedup vs baseline: 1.0398x; 1.0398x over previous
#include <cuda_runtime.h>
#include <cuda_bf16.h>
#include <stdint.h>
#include <math.h>

#define NN 4096
#define HH 256
#define EE 65536
#define SPLITS 8
#define CC 1024   // combined xlin|q|k|v row width

// ---------------- device scratch ----------------
__device__ float g_h[NN * HH];
__device__ float g_comb[NN * CC];     // [xlin fp32 | Q bits*0.125 | K bits | V bits]
__device__ float g_attn[NN * HH];
__device__ float g_out[NN * HH];
__device__ float g_ffn[NN * 2 * HH];
__device__ float g_hid[NN * HH];
__device__ float g_deg[NN];
__device__ float g_dinv[NN];
__device__ float g_opart[SPLITS * NN * HH];
__device__ float g_mpart[SPLITS * 4 * NN];
__device__ float g_lpart[SPLITS * 4 * NN];

// ---------------- helpers ----------------
__device__ __forceinline__ uint32_t f2tf(float f) {
    uint32_t u;
    asm("cvt.rna.tf32.f32 %0, %1;" : "=r"(u) : "f"(f));
    return u;
}

__device__ __forceinline__ void mma_tf32(float c[4], const uint32_t a[4], const uint32_t b[2]) {
    asm volatile(
        "mma.sync.aligned.m16n8k8.row.col.f32.tf32.tf32.f32 "
        "{%0,%1,%2,%3},{%4,%5,%6,%7},{%8,%9},{%0,%1,%2,%3};\n"
        : "+f"(c[0]), "+f"(c[1]), "+f"(c[2]), "+f"(c[3])
        : "r"(a[0]), "r"(a[1]), "r"(a[2]), "r"(a[3]), "r"(b[0]), "r"(b[1]));
}

__device__ __forceinline__ void cpa16(void* s, const void* g) {
    uint32_t sa = (uint32_t)__cvta_generic_to_shared(s);
    asm volatile("cp.async.cg.shared.global [%0], [%1], 16;\n" :: "r"(sa), "l"(g) : "memory");
}
#define CP_COMMIT asm volatile("cp.async.commit_group;\n" ::: "memory")
template<int W> __device__ __forceinline__ void cp_wait() {
    asm volatile("cp.async.wait_group %0;\n" :: "n"(W) : "memory");
}

__device__ __forceinline__ void red4(float* addr, float a, float b, float c, float d) {
    asm volatile("red.global.add.v4.f32 [%0], {%1,%2,%3,%4};"
                 :: "l"(addr), "f"(a), "f"(b), "f"(c), "f"(d) : "memory");
}

// ---------------- TF32 GEMM: 64x64 tile, 4 warps, 3-stage (round-8 core) ----------------
// C = act(A @ Wsel^T + biassel + addscale*add)
// Wsel/biassel: column tiles with n0 < wsplit use (W, bias); others use (W2, bias2) shifted.
// outmode: 0 = fp32, 1 = tf32 bits, 2 = comb (nn<HH fp32; HH<=nn<2HH bits*0.125; else bits)
#define GBK 16

__global__ void __launch_bounds__(128) tgemm(
    const float* __restrict__ A, const float* __restrict__ W, const float* __restrict__ W2,
    int wsplit, const float* __restrict__ bias, const float* __restrict__ bias2,
    const float* __restrict__ add, float addscale,
    float* __restrict__ C, int M, int Nn, int K, int relu, int outmode) {
    __shared__ float As[3][64][20];
    __shared__ float Ws[3][64][20];

    int tid = threadIdx.x;
    int lane = tid & 31, wid = tid >> 5;
    int warp_m = wid & 1, warp_n = wid >> 1;
    int m0 = blockIdx.y * 64, n0 = blockIdx.x * 64;

    const float* Wb;
    const float* bb;
    int bshift;
    if (n0 < wsplit) { Wb = W  + (long)n0 * K;            bb = bias;  bshift = 0; }
    else             { Wb = W2 + (long)(n0 - wsplit) * K; bb = bias2; bshift = wsplit; }

    float c[2][4][4];
#pragma unroll
    for (int mt = 0; mt < 2; mt++)
#pragma unroll
        for (int nt = 0; nt < 4; nt++)
#pragma unroll
            for (int r = 0; r < 4; r++) c[mt][nt][r] = 0.f;

    int nIter = K / GBK;

    auto issue = [&](int it, int buf) {
        int k0 = it * GBK;
#pragma unroll
        for (int j = 0; j < 2; j++) {
            int cc = tid + 128 * j;
            int row = cc >> 2, ch = (cc & 3) * 4;
            cpa16(&As[buf][row][ch], &A[(long)(m0 + row) * K + k0 + ch]);
            cpa16(&Ws[buf][row][ch], &Wb[(long)row * K + k0 + ch]);
        }
    };

    issue(0, 0); CP_COMMIT;
    issue(1, 1); CP_COMMIT;

    for (int i = 0; i < nIter; i++) {
        int buf = i % 3;
        if (i + 2 < nIter) { issue(i + 2, (i + 2) % 3); CP_COMMIT; cp_wait<2>(); }
        else if (i + 1 < nIter) cp_wait<1>();
        else cp_wait<0>();
        __syncthreads();

#pragma unroll
        for (int ks = 0; ks < GBK; ks += 8) {
            uint32_t a[2][4], b[4][2];
            int kk = ks + (lane & 3);
#pragma unroll
            for (int mt = 0; mt < 2; mt++) {
                int row = warp_m * 32 + mt * 16 + (lane >> 2);
                a[mt][0] = f2tf(As[buf][row][kk]);
                a[mt][1] = f2tf(As[buf][row + 8][kk]);
                a[mt][2] = f2tf(As[buf][row][kk + 4]);
                a[mt][3] = f2tf(As[buf][row + 8][kk + 4]);
            }
#pragma unroll
            for (int nt = 0; nt < 4; nt++) {
                int nc = warp_n * 32 + nt * 8 + (lane >> 2);
                b[nt][0] = f2tf(Ws[buf][nc][kk]);
                b[nt][1] = f2tf(Ws[buf][nc][kk + 4]);
            }
#pragma unroll
            for (int mt = 0; mt < 2; mt++)
#pragma unroll
                for (int nt = 0; nt < 4; nt++) mma_tf32(c[mt][nt], a[mt], b[nt]);
        }
        __syncthreads();
    }

    // epilogue
#pragma unroll
    for (int mt = 0; mt < 2; mt++) {
        int rb = m0 + warp_m * 32 + mt * 16 + (lane >> 2);
#pragma unroll
        for (int nt = 0; nt < 4; nt++) {
            int cb = n0 + warp_n * 32 + nt * 8 + 2 * (lane & 3);
#pragma unroll
            for (int r = 0; r < 4; r++) {
                int mm = rb + (r >> 1) * 8;
                int nn = cb + (r & 1);
                float v = c[mt][nt][r];
                if (bb)  v += bb[nn - bshift];
                if (add) v += addscale * add[(long)mm * HH + nn];   // add is always [M,HH]
                if (relu) v = fmaxf(v, 0.f);
                if (outmode == 0) {
                    C[(long)mm * Nn + nn] = v;
                } else if (outmode == 1) {
                    C[(long)mm * Nn + nn] = __uint_as_float(f2tf(v));
                } else {
                    if (nn < HH)          C[(long)mm * Nn + nn] = v;                // xlin fp32
                    else {
                        if (nn < 2 * HH) v *= 0.125f;                               // Q pre-scale
                        C[(long)mm * Nn + nn] = __uint_as_float(f2tf(v));
                    }
                }
            }
        }
    }
}

// ---------------- TF32 flash attention (comb holds tf32 bits for Q/K/V) ----------------
#define KST 68
#define VST 72
#define KBUF (64 * KST)
#define VBUF (64 * VST)

__global__ void __launch_bounds__(128) flash_part(const float* __restrict__ comb,
                                                  float* __restrict__ opart,
                                                  float* __restrict__ mpart,
                                                  float* __restrict__ lpart) {
    extern __shared__ float sm[];
    float* Ks = sm;                 // [2][64][KST]; reused as P after S-matmul
    float* Vs = sm + 2 * KBUF;      // [2][64][VST]

    int tid = threadIdx.x;
    int lane = tid & 31, wid = tid >> 5;
    int q0 = blockIdx.x * 64;
    int head = blockIdx.y;
    int split = blockIdx.z;
    const int qoff = HH + head * 64, koff = 2 * HH + head * 64, voff = 3 * HH + head * 64;

    uint32_t qa[8][4];
    {
        int r = q0 + wid * 16 + (lane >> 2);
#pragma unroll
        for (int kt = 0; kt < 8; kt++) {
            int d = kt * 8 + (lane & 3);
            qa[kt][0] = __float_as_uint(comb[(long)r * CC + qoff + d]);
            qa[kt][1] = __float_as_uint(comb[(long)(r + 8) * CC + qoff + d]);
            qa[kt][2] = __float_as_uint(comb[(long)r * CC + qoff + d + 4]);
            qa[kt][3] = __float_as_uint(comb[(long)(r + 8) * CC + qoff + d + 4]);
        }
    }

    float m0 = -1e30f, m1 = -1e30f, l0 = 0.f, l1 = 0.f;
    float o[8][4];
#pragma unroll
    for (int nt = 0; nt < 8; nt++)
#pragma unroll
        for (int r = 0; r < 4; r++) o[nt][r] = 0.f;

    int kbase = split * (NN / SPLITS);
    const int nIter = (NN / SPLITS) / 64;

    auto issue = [&](int it, int buf) {
        int k0 = kbase + it * 64;
#pragma unroll
        for (int j = 0; j < 8; j++) {
            int cc = tid + 128 * j;
            int key = cc >> 4, ch = (cc & 15) * 4;
            cpa16(&Ks[buf * KBUF + key * KST + ch], &comb[(long)(k0 + key) * CC + koff + ch]);
            cpa16(&Vs[buf * VBUF + key * VST + ch], &comb[(long)(k0 + key) * CC + voff + ch]);
        }
    };

    issue(0, 0); CP_COMMIT;
    int cur = 0;
    for (int i = 0; i < nIter; i++) {
        if (i + 1 < nIter) { issue(i + 1, cur ^ 1); CP_COMMIT; cp_wait<1>(); }
        else cp_wait<0>();
        __syncthreads();

        float* Kc = Ks + cur * KBUF;
        const float* Vc = Vs + cur * VBUF;

        float s[8][4];
#pragma unroll
        for (int nt = 0; nt < 8; nt++)
#pragma unroll
            for (int r = 0; r < 4; r++) s[nt][r] = 0.f;
#pragma unroll
        for (int kt = 0; kt < 8; kt++) {
            int kk = kt * 8 + (lane & 3);
            uint32_t b[2];
#pragma unroll
            for (int nt = 0; nt < 8; nt++) {
                int key = nt * 8 + (lane >> 2);
                b[0] = __float_as_uint(Kc[key * KST + kk]);
                b[1] = __float_as_uint(Kc[key * KST + kk + 4]);
                mma_tf32(s[nt], qa[kt], b);
            }
        }

        float mx0 = -1e30f, mx1 = -1e30f;
#pragma unroll
        for (int nt = 0; nt < 8; nt++) {
            mx0 = fmaxf(mx0, fmaxf(s[nt][0], s[nt][1]));
            mx1 = fmaxf(mx1, fmaxf(s[nt][2], s[nt][3]));
        }
#pragma unroll
        for (int off = 1; off <= 2; off <<= 1) {
            mx0 = fmaxf(mx0, __shfl_xor_sync(0xffffffffu, mx0, off));
            mx1 = fmaxf(mx1, __shfl_xor_sync(0xffffffffu, mx1, off));
        }
        float mn0 = fmaxf(m0, mx0), mn1 = fmaxf(m1, mx1);
        float sum0 = 0.f, sum1 = 0.f;
#pragma unroll
        for (int nt = 0; nt < 8; nt++) {
            s[nt][0] = __expf(s[nt][0] - mn0);
            s[nt][1] = __expf(s[nt][1] - mn0);
            s[nt][2] = __expf(s[nt][2] - mn1);
            s[nt][3] = __expf(s[nt][3] - mn1);
            sum0 += s[nt][0] + s[nt][1];
            sum1 += s[nt][2] + s[nt][3];
        }
#pragma unroll
        for (int off = 1; off <= 2; off <<= 1) {
            sum0 += __shfl_xor_sync(0xffffffffu, sum0, off);
            sum1 += __shfl_xor_sync(0xffffffffu, sum1, off);
        }
        float e0 = __expf(m0 - mn0), e1 = __expf(m1 - mn1);
        l0 = l0 * e0 + sum0;
        l1 = l1 * e1 + sum1;
        m0 = mn0; m1 = mn1;
#pragma unroll
        for (int nt = 0; nt < 8; nt++) {
            o[nt][0] *= e0; o[nt][1] *= e0;
            o[nt][2] *= e1; o[nt][3] *= e1;
        }

        __syncthreads();   // Kc readers done -> reuse as P

        {
            int r = wid * 16 + (lane >> 2);
#pragma unroll
            for (int nt = 0; nt < 8; nt++) {
                int cb = nt * 8 + 2 * (lane & 3);
                Kc[r * KST + cb]           = __uint_as_float(f2tf(s[nt][0]));
                Kc[r * KST + cb + 1]       = __uint_as_float(f2tf(s[nt][1]));
                Kc[(r + 8) * KST + cb]     = __uint_as_float(f2tf(s[nt][2]));
                Kc[(r + 8) * KST + cb + 1] = __uint_as_float(f2tf(s[nt][3]));
            }
        }
        __syncwarp();

#pragma unroll
        for (int kt = 0; kt < 8; kt++) {
            int r = wid * 16 + (lane >> 2);
            int kk = kt * 8 + (lane & 3);
            uint32_t a[4];
            a[0] = __float_as_uint(Kc[r * KST + kk]);
            a[1] = __float_as_uint(Kc[(r + 8) * KST + kk]);
            a[2] = __float_as_uint(Kc[r * KST + kk + 4]);
            a[3] = __float_as_uint(Kc[(r + 8) * KST + kk + 4]);
            uint32_t b[2];
#pragma unroll
            for (int nt = 0; nt < 8; nt++) {
                int dd = nt * 8 + (lane >> 2);
                b[0] = __float_as_uint(Vc[kk * VST + dd]);
                b[1] = __float_as_uint(Vc[(kk + 4) * VST + dd]);
                mma_tf32(o[nt], a, b);
            }
        }
        __syncthreads();
        cur ^= 1;
    }

    int r = q0 + wid * 16 + (lane >> 2);
    float* ob = opart + (long)split * NN * HH;
#pragma unroll
    for (int nt = 0; nt < 8; nt++) {
        int cb = head * 64 + nt * 8 + 2 * (lane & 3);
        ob[(long)r * HH + cb]           = o[nt][0];
        ob[(long)r * HH + cb + 1]       = o[nt][1];
        ob[(long)(r + 8) * HH + cb]     = o[nt][2];
        ob[(long)(r + 8) * HH + cb + 1] = o[nt][3];
    }
    if ((lane & 3) == 0) {
        int base = (split * 4 + head) * NN;
        mpart[base + r] = m0;     lpart[base + r] = l0;
        mpart[base + r + 8] = m1; lpart[base + r + 8] = l1;
    }
}

__global__ void flash_merge(const float* __restrict__ opart, const float* __restrict__ mpart,
                            const float* __restrict__ lpart, float* __restrict__ out) {
    int idx = blockIdx.x * blockDim.x + threadIdx.x;
    if (idx >= NN * HH) return;
    int row = idx >> 8, c = idx & 255, head = c >> 6;
    float mv[SPLITS], lv[SPLITS];
    float mmax = -1e30f;
#pragma unroll
    for (int s = 0; s < SPLITS; s++) {
        mv[s] = mpart[(s * 4 + head) * NN + row];
        lv[s] = lpart[(s * 4 + head) * NN + row];
        mmax = fmaxf(mmax, mv[s]);
    }
    float num = 0.f, den = 0.f;
#pragma unroll
    for (int s = 0; s < SPLITS; s++) {
        float w = __expf(mv[s] - mmax);
        num += opart[(long)s * NN * HH + idx] * w;
        den += lv[s] * w;
    }
    out[idx] = num / den;
}

// ---------------- GCN helpers ----------------
__global__ void deg_init(float* deg, int n) {
    int i = blockIdx.x * blockDim.x + threadIdx.x;
    if (i < n) deg[i] = 1.f;
}
__global__ void deg_count(const int* __restrict__ dst, float* deg, int e) {
    int i = blockIdx.x * blockDim.x + threadIdx.x;
    if (i < e) atomicAdd(&deg[dst[i]], 1.f);
}
__global__ void dinv_kernel(const float* __restrict__ deg, float* dinv, int n) {
    int i = blockIdx.x * blockDim.x + threadIdx.x;
    if (i < n) dinv[i] = rsqrtf(deg[i]);
}

// scatter directly into outb (= proj + 2h + out_b, already written by proj GEMM)
__global__ void gcn_scatter(const int* __restrict__ src, const int* __restrict__ dst,
                            const float* __restrict__ dinv, const float* __restrict__ comb,
                            float* __restrict__ outb, int e) {
    int w = (blockIdx.x * blockDim.x + threadIdx.x) >> 5;
    int lane = threadIdx.x & 31;
    if (w >= e) return;
    int s = src[w], d = dst[w];
    float coef = dinv[s] * dinv[d];
    const float4* xs = (const float4*)(comb + (long)s * CC);   // xlin = cols [0,256)
    float* ad = outb + (long)d * HH;
    float4 v0 = xs[lane];
    float4 v1 = xs[lane + 32];
    red4(ad + lane * 4,       v0.x * coef, v0.y * coef, v0.z * coef, v0.w * coef);
    red4(ad + 128 + lane * 4, v1.x * coef, v1.y * coef, v1.z * coef, v1.w * coef);
}

// outb += xlin * dinv^2 (self loop) + gcn_b
__global__ void combine2(float* __restrict__ outb, const float* __restrict__ comb,
                         const float* __restrict__ dinv, const float* __restrict__ gcn_b,
                         int total) {
    int idx = blockIdx.x * blockDim.x + threadIdx.x;
    if (idx >= total) return;
    int i = idx >> 8, c = idx & 255;
    float dv = dinv[i];
    outb[idx] += comb[(long)i * CC + c] * dv * dv + gcn_b[c];
}

// ---------------- tiled symmetrize ----------------
__global__ void __launch_bounds__(256) symmetrize(float* __restrict__ o) {
    int ti = blockIdx.y, tj = blockIdx.x;
    if (tj < ti) return;
    __shared__ float As[64][65];
    __shared__ float Bs[64][65];
    int tid = threadIdx.x;
    int r = tid >> 2, c0 = (tid & 3) * 16;
    long base_a = (long)ti * 64 * NN + tj * 64;
    long base_b = (long)tj * 64 * NN + ti * 64;

#pragma unroll
    for (int j = 0; j < 16; j += 4) {
        float4 va = *(const float4*)&o[base_a + (long)r * NN + c0 + j];
        float4 vb = *(const float4*)&o[base_b + (long)r * NN + c0 + j];
        As[r][c0 + j] = va.x; As[r][c0 + j + 1] = va.y;
        As[r][c0 + j + 2] = va.z; As[r][c0 + j + 3] = va.w;
        Bs[r][c0 + j] = vb.x; Bs[r][c0 + j + 1] = vb.y;
        Bs[r][c0 + j + 2] = vb.z; Bs[r][c0 + j + 3] = vb.w;
    }
    __syncthreads();

#pragma unroll
    for (int j = 0; j < 16; j += 4) {
        float4 wa, wb;
        wa.x = 0.5f * (As[r][c0 + j]     + Bs[c0 + j][r]);
        wa.y = 0.5f * (As[r][c0 + j + 1] + Bs[c0 + j + 1][r]);
        wa.z = 0.5f * (As[r][c0 + j + 2] + Bs[c0 + j + 2][r]);
        wa.w = 0.5f * (As[r][c0 + j + 3] + Bs[c0 + j + 3][r]);
        *(float4*)&o[base_a + (long)r * NN + c0 + j] = wa;
        if (ti != tj) {
            wb.x = 0.5f * (Bs[r][c0 + j]     + As[c0 + j][r]);
            wb.y = 0.5f * (Bs[r][c0 + j + 1] + As[c0 + j + 1][r]);
            wb.z = 0.5f * (Bs[r][c0 + j + 2] + As[c0 + j + 2][r]);
            wb.w = 0.5f * (Bs[r][c0 + j + 3] + As[c0 + j + 3][r]);
            *(float4*)&o[base_b + (long)r * NN + c0 + j] = wb;
        }
    }
}

// ---------------- launch ----------------
extern "C" void kernel_launch(void* const* d_in, const int* in_sizes, int n_in,
                              void* d_out, int out_size) {
    const float* x      = (const float*)d_in[0];
    const int*   ei     = (const int*)d_in[1];
    const float* pre_w  = (const float*)d_in[2];
    const float* pre_b  = (const float*)d_in[3];
    const float* mlp_w1 = (const float*)d_in[24];
    const float* mlp_b1 = (const float*)d_in[25];
    const float* mlp_w2 = (const float*)d_in[26];
    const float* mlp_b2 = (const float*)d_in[27];

    float *h, *comb, *attn, *outb, *ffn, *hid, *deg, *dinv;
    float *opart, *mpart, *lpart;
    cudaGetSymbolAddress((void**)&h,    g_h);
    cudaGetSymbolAddress((void**)&comb, g_comb);
    cudaGetSymbolAddress((void**)&attn, g_attn);
    cudaGetSymbolAddress((void**)&outb, g_out);
    cudaGetSymbolAddress((void**)&ffn,  g_ffn);
    cudaGetSymbolAddress((void**)&hid,  g_hid);
    cudaGetSymbolAddress((void**)&deg,  g_deg);
    cudaGetSymbolAddress((void**)&dinv, g_dinv);
    cudaGetSymbolAddress((void**)&opart, g_opart);
    cudaGetSymbolAddress((void**)&mpart, g_mpart);
    cudaGetSymbolAddress((void**)&lpart, g_lpart);

    const int flash_smem = (2 * KBUF + 2 * VBUF) * (int)sizeof(float);  // 71680
    cudaFuncSetAttribute(flash_part, cudaFuncAttributeMaxDynamicSharedMemorySize, flash_smem);

    const int BIG = 1 << 30;

    deg_init<<<(NN + 255) / 256, 256>>>(deg, NN);
    deg_count<<<(EE + 255) / 256, 256>>>(ei + EE, deg, EE);
    dinv_kernel<<<(NN + 255) / 256, 256>>>(deg, dinv, NN);

    // pre: h = relu(x @ pre_w^T + pre_b)  (fp32)
    tgemm<<<dim3(HH / 64, NN / 64), 128>>>(x, pre_w, pre_w, BIG, pre_b, nullptr,
                                           nullptr, 0.f, h, NN, HH, 128, 1, 0);

    for (int L = 0; L < 2; L++) {
        int base = 4 + L * 10;
        const float* gcn_w  = (const float*)d_in[base + 0];
        const float* gcn_b  = (const float*)d_in[base + 1];
        const float* in_w   = (const float*)d_in[base + 2];
        const float* in_b   = (const float*)d_in[base + 3];
        const float* out_w  = (const float*)d_in[base + 4];
        const float* out_b  = (const float*)d_in[base + 5];
        const float* ffn_w1 = (const float*)d_in[base + 6];
        const float* ffn_b1 = (const float*)d_in[base + 7];
        const float* ffn_w2 = (const float*)d_in[base + 8];
        const float* ffn_b2 = (const float*)d_in[base + 9];

        // fused xlin|qkv GEMM: cols [0,256)=gcn_w (fp32 out), [256,1024)=in_w (bits out, Q scaled)
        tgemm<<<dim3(CC / 64, NN / 64), 128>>>(h, gcn_w, in_w, HH, nullptr, in_b,
                                               nullptr, 0.f, comb, NN, CC, HH, 0, 2);
        flash_part<<<dim3(NN / 64, 4, SPLITS), 128, flash_smem>>>(comb, opart, mpart, lpart);
        flash_merge<<<(NN * HH) / 256, 256>>>(opart, mpart, lpart, attn);
        // proj GEMM fused with GPS residuals: outb = attn@out_w + out_b + 2*h
        tgemm<<<dim3(HH / 64, NN / 64), 128>>>(attn, out_w, out_w, BIG, out_b, nullptr,
                                               h, 2.f, outb, NN, HH, HH, 0, 0);
        // GCN aggregation straight into outb
        gcn_scatter<<<(EE * 32) / 256, 256>>>(ei, ei + EE, dinv, comb, outb, EE);
        combine2<<<(NN * HH) / 256, 256>>>(outb, comb, dinv, gcn_b, NN * HH);
        // FFN
        tgemm<<<dim3(2 * HH / 64, NN / 64), 128>>>(outb, ffn_w1, ffn_w1, BIG, ffn_b1, nullptr,
                                                   nullptr, 0.f, ffn, NN, 2 * HH, HH, 1, 0);
        tgemm<<<dim3(HH / 64, NN / 64), 128>>>(ffn, ffn_w2, ffn_w2, BIG, ffn_b2, nullptr,
                                               outb, 1.f, h, NN, HH, 2 * HH, 1, 0);
    }

    // head
    tgemm<<<dim3(HH / 64, NN / 64), 128>>>(h, mlp_w1, mlp_w1, BIG, mlp_b1, nullptr,
                                           nullptr, 0.f, hid, NN, HH, HH, 1, 0);
    tgemm<<<dim3(NN / 64, NN / 64), 128>>>(hid, mlp_w2, mlp_w2, BIG, mlp_b2, nullptr,
                                           nullptr, 0.f, (float*)d_out, NN, NN, HH, 0, 0);
    symmetrize<<<dim3(NN / 64, NN / 64), 256>>>((float*)d_out);
}

// round 11
// speedup vs baseline: 1.1034x; 1.0612x over previous
#include <cuda_runtime.h>
#include <cuda_bf16.h>
#include <stdint.h>
#include <math.h>

#define NN 4096
#define HH 256
#define EE 65536
#define SPLITS 8
#define CC 1024   // combined xlin|q|k|v row width

// ---------------- device scratch ----------------
__device__ float g_h[NN * HH];
__device__ float g_comb[NN * CC];     // [xlin fp32 | Q bits*0.125 | K bits | V bits]
__device__ float g_attn[NN * HH];
__device__ float g_out[NN * HH];
__device__ float g_ffn[NN * 2 * HH];
__device__ float g_hid[NN * HH];
__device__ float g_deg[NN];
__device__ float g_dinv[NN];
__device__ float g_opart[SPLITS * NN * HH];
__device__ float g_mpart[SPLITS * 4 * NN];
__device__ float g_lpart[SPLITS * 4 * NN];

// ---------------- helpers ----------------
__device__ __forceinline__ uint32_t f2tf(float f) {
    uint32_t u;
    asm("cvt.rna.tf32.f32 %0, %1;" : "=r"(u) : "f"(f));
    return u;
}

__device__ __forceinline__ void mma_tf32(float c[4], const uint32_t a[4], const uint32_t b[2]) {
    asm volatile(
        "mma.sync.aligned.m16n8k8.row.col.f32.tf32.tf32.f32 "
        "{%0,%1,%2,%3},{%4,%5,%6,%7},{%8,%9},{%0,%1,%2,%3};\n"
        : "+f"(c[0]), "+f"(c[1]), "+f"(c[2]), "+f"(c[3])
        : "r"(a[0]), "r"(a[1]), "r"(a[2]), "r"(a[3]), "r"(b[0]), "r"(b[1]));
}

__device__ __forceinline__ void cpa16(void* s, const void* g) {
    uint32_t sa = (uint32_t)__cvta_generic_to_shared(s);
    asm volatile("cp.async.cg.shared.global [%0], [%1], 16;\n" :: "r"(sa), "l"(g) : "memory");
}
#define CP_COMMIT asm volatile("cp.async.commit_group;\n" ::: "memory")
template<int W> __device__ __forceinline__ void cp_wait() {
    asm volatile("cp.async.wait_group %0;\n" :: "n"(W) : "memory");
}

__device__ __forceinline__ void red4(float* addr, float a, float b, float c, float d) {
    asm volatile("red.global.add.v4.f32 [%0], {%1,%2,%3,%4};"
                 :: "l"(addr), "f"(a), "f"(b), "f"(c), "f"(d) : "memory");
}

// ---------------- TF32 GEMM: 64x64 tile, 4 warps, 3-stage ----------------
// C = act(A @ Wsel^T + biassel + addscale*add)
#define GBK 16

__global__ void __launch_bounds__(128) tgemm(
    const float* __restrict__ A, const float* __restrict__ W, const float* __restrict__ W2,
    int wsplit, const float* __restrict__ bias, const float* __restrict__ bias2,
    const float* __restrict__ add, float addscale,
    float* __restrict__ C, int M, int Nn, int K, int relu, int outmode) {
    __shared__ float As[3][64][20];
    __shared__ float Ws[3][64][20];

    int tid = threadIdx.x;
    int lane = tid & 31, wid = tid >> 5;
    int warp_m = wid & 1, warp_n = wid >> 1;
    int m0 = blockIdx.y * 64, n0 = blockIdx.x * 64;

    const float* Wb;
    const float* bb;
    int bshift;
    if (n0 < wsplit) { Wb = W  + (long)n0 * K;            bb = bias;  bshift = 0; }
    else             { Wb = W2 + (long)(n0 - wsplit) * K; bb = bias2; bshift = wsplit; }

    float c[2][4][4];
#pragma unroll
    for (int mt = 0; mt < 2; mt++)
#pragma unroll
        for (int nt = 0; nt < 4; nt++)
#pragma unroll
            for (int r = 0; r < 4; r++) c[mt][nt][r] = 0.f;

    int nIter = K / GBK;

    auto issue = [&](int it, int buf) {
        int k0 = it * GBK;
#pragma unroll
        for (int j = 0; j < 2; j++) {
            int cc = tid + 128 * j;
            int row = cc >> 2, ch = (cc & 3) * 4;
            cpa16(&As[buf][row][ch], &A[(long)(m0 + row) * K + k0 + ch]);
            cpa16(&Ws[buf][row][ch], &Wb[(long)row * K + k0 + ch]);
        }
    };

    issue(0, 0); CP_COMMIT;
    issue(1, 1); CP_COMMIT;

    for (int i = 0; i < nIter; i++) {
        int buf = i % 3;
        if (i + 2 < nIter) { issue(i + 2, (i + 2) % 3); CP_COMMIT; cp_wait<2>(); }
        else if (i + 1 < nIter) cp_wait<1>();
        else cp_wait<0>();
        __syncthreads();

#pragma unroll
        for (int ks = 0; ks < GBK; ks += 8) {
            uint32_t a[2][4], b[4][2];
            int kk = ks + (lane & 3);
#pragma unroll
            for (int mt = 0; mt < 2; mt++) {
                int row = warp_m * 32 + mt * 16 + (lane >> 2);
                a[mt][0] = f2tf(As[buf][row][kk]);
                a[mt][1] = f2tf(As[buf][row + 8][kk]);
                a[mt][2] = f2tf(As[buf][row][kk + 4]);
                a[mt][3] = f2tf(As[buf][row + 8][kk + 4]);
            }
#pragma unroll
            for (int nt = 0; nt < 4; nt++) {
                int nc = warp_n * 32 + nt * 8 + (lane >> 2);
                b[nt][0] = f2tf(Ws[buf][nc][kk]);
                b[nt][1] = f2tf(Ws[buf][nc][kk + 4]);
            }
#pragma unroll
            for (int mt = 0; mt < 2; mt++)
#pragma unroll
                for (int nt = 0; nt < 4; nt++) mma_tf32(c[mt][nt], a[mt], b[nt]);
        }
        __syncthreads();
    }

#pragma unroll
    for (int mt = 0; mt < 2; mt++) {
        int rb = m0 + warp_m * 32 + mt * 16 + (lane >> 2);
#pragma unroll
        for (int nt = 0; nt < 4; nt++) {
            int cb = n0 + warp_n * 32 + nt * 8 + 2 * (lane & 3);
#pragma unroll
            for (int r = 0; r < 4; r++) {
                int mm = rb + (r >> 1) * 8;
                int nn = cb + (r & 1);
                float v = c[mt][nt][r];
                if (bb)  v += bb[nn - bshift];
                if (add) v += addscale * add[(long)mm * HH + nn];
                if (relu) v = fmaxf(v, 0.f);
                if (outmode == 0) {
                    C[(long)mm * Nn + nn] = v;
                } else if (outmode == 1) {
                    C[(long)mm * Nn + nn] = __uint_as_float(f2tf(v));
                } else {
                    if (nn < HH)          C[(long)mm * Nn + nn] = v;
                    else {
                        if (nn < 2 * HH) v *= 0.125f;
                        C[(long)mm * Nn + nn] = __uint_as_float(f2tf(v));
                    }
                }
            }
        }
    }
}

// ---------------- head GEMM fused with symmetrize ----------------
// For tile pair (ti,tj), tj>=ti: c1 = hid_i @ W_j^T, c2 = hid_j @ W_i^T,
// out_ij = 0.5*(c1 + b[n] + c2^T + b[m]); out_ji = out_ij^T.
#define TRST 68

__global__ void __launch_bounds__(128) mlp2_sym(
    const float* __restrict__ A, const float* __restrict__ W,
    const float* __restrict__ bias, float* __restrict__ C) {
    int ti = blockIdx.y, tj = blockIdx.x;
    if (tj < ti) return;
    extern __shared__ float sm[];
    float* Hi = sm;            // [3][64][20]
    float* Hj = sm + 3840;
    float* Wj = sm + 7680;
    float* Wi = sm + 11520;

    int tid = threadIdx.x;
    int lane = tid & 31, wid = tid >> 5;
    int warp_m = wid & 1, warp_n = wid >> 1;
    int mi0 = ti * 64, mj0 = tj * 64;

    float c1[2][4][4], c2[2][4][4];
#pragma unroll
    for (int mt = 0; mt < 2; mt++)
#pragma unroll
        for (int nt = 0; nt < 4; nt++)
#pragma unroll
            for (int r = 0; r < 4; r++) { c1[mt][nt][r] = 0.f; c2[mt][nt][r] = 0.f; }

    const int nIter = HH / GBK;   // 16

    auto issue = [&](int it, int buf) {
        int k0 = it * GBK;
        long bb = (long)buf * 1280;
#pragma unroll
        for (int j = 0; j < 2; j++) {
            int cc = tid + 128 * j;
            int row = cc >> 2, ch = (cc & 3) * 4;
            long so = bb + row * 20 + ch;
            cpa16(&Hi[so], &A[(long)(mi0 + row) * HH + k0 + ch]);
            cpa16(&Hj[so], &A[(long)(mj0 + row) * HH + k0 + ch]);
            cpa16(&Wj[so], &W[(long)(mj0 + row) * HH + k0 + ch]);
            cpa16(&Wi[so], &W[(long)(mi0 + row) * HH + k0 + ch]);
        }
    };

    issue(0, 0); CP_COMMIT;
    issue(1, 1); CP_COMMIT;

    for (int i = 0; i < nIter; i++) {
        int buf = i % 3;
        if (i + 2 < nIter) { issue(i + 2, (i + 2) % 3); CP_COMMIT; cp_wait<2>(); }
        else if (i + 1 < nIter) cp_wait<1>();
        else cp_wait<0>();
        __syncthreads();

        long bb = (long)buf * 1280;
#pragma unroll
        for (int ks = 0; ks < GBK; ks += 8) {
            uint32_t a1[2][4], a2[2][4], b1[4][2], b2[4][2];
            int kk = ks + (lane & 3);
#pragma unroll
            for (int mt = 0; mt < 2; mt++) {
                int row = warp_m * 32 + mt * 16 + (lane >> 2);
                long o0 = bb + row * 20 + kk, o1 = bb + (row + 8) * 20 + kk;
                a1[mt][0] = f2tf(Hi[o0]);     a1[mt][1] = f2tf(Hi[o1]);
                a1[mt][2] = f2tf(Hi[o0 + 4]); a1[mt][3] = f2tf(Hi[o1 + 4]);
                a2[mt][0] = f2tf(Hj[o0]);     a2[mt][1] = f2tf(Hj[o1]);
                a2[mt][2] = f2tf(Hj[o0 + 4]); a2[mt][3] = f2tf(Hj[o1 + 4]);
            }
#pragma unroll
            for (int nt = 0; nt < 4; nt++) {
                int nc = warp_n * 32 + nt * 8 + (lane >> 2);
                long o = bb + nc * 20 + kk;
                b1[nt][0] = f2tf(Wj[o]); b1[nt][1] = f2tf(Wj[o + 4]);
                b2[nt][0] = f2tf(Wi[o]); b2[nt][1] = f2tf(Wi[o + 4]);
            }
#pragma unroll
            for (int mt = 0; mt < 2; mt++)
#pragma unroll
                for (int nt = 0; nt < 4; nt++) {
                    mma_tf32(c1[mt][nt], a1[mt], b1[nt]);
                    mma_tf32(c2[mt][nt], a2[mt], b2[nt]);
                }
        }
        __syncthreads();
    }

    // epilogue: transpose c2 through smem, symmetrize, write both tiles
    float* Tr  = sm;                 // [64][TRST]
    float* Tr2 = sm + 64 * TRST;     // [64][TRST]

#pragma unroll
    for (int mt = 0; mt < 2; mt++) {
        int rb = warp_m * 32 + mt * 16 + (lane >> 2);
#pragma unroll
        for (int nt = 0; nt < 4; nt++) {
            int cb = warp_n * 32 + nt * 8 + 2 * (lane & 3);
#pragma unroll
            for (int r = 0; r < 4; r++)
                Tr[(rb + (r >> 1) * 8) * TRST + cb + (r & 1)] = c2[mt][nt][r];
        }
    }
    __syncthreads();

#pragma unroll
    for (int mt = 0; mt < 2; mt++) {
        int rb = warp_m * 32 + mt * 16 + (lane >> 2);
#pragma unroll
        for (int nt = 0; nt < 4; nt++) {
            int cb = warp_n * 32 + nt * 8 + 2 * (lane & 3);
#pragma unroll
            for (int r = 0; r < 4; r++) {
                int mloc = rb + (r >> 1) * 8;
                int nloc = cb + (r & 1);
                float v = 0.5f * (c1[mt][nt][r] + bias[mj0 + nloc]
                                  + Tr[nloc * TRST + mloc] + bias[mi0 + mloc]);
                C[(long)(mi0 + mloc) * NN + mj0 + nloc] = v;
                Tr2[nloc * TRST + mloc] = v;
            }
        }
    }

    if (ti != tj) {
        __syncthreads();
        int row = tid >> 1, half = tid & 1;
        long base = (long)(mj0 + row) * NN + mi0 + half * 32;
        const float* tr = Tr2 + row * TRST + half * 32;
#pragma unroll
        for (int k = 0; k < 32; k += 4)
            *(float4*)&C[base + k] = *(const float4*)&tr[k];
    }
}

// ---------------- TF32 flash attention: BM=128, 256 thr, dedicated P ----------------
#define KST 68
#define VST 72
#define KBUF (64 * KST)
#define VBUF (64 * VST)

__global__ void __launch_bounds__(256) flash_part(const float* __restrict__ comb,
                                                  float* __restrict__ opart,
                                                  float* __restrict__ mpart,
                                                  float* __restrict__ lpart) {
    extern __shared__ float sm[];
    float* Ks = sm;                          // [2][64][KST]
    float* Vs = sm + 2 * KBUF;               // [2][64][VST]
    float* Ps = sm + 2 * KBUF + 2 * VBUF;    // [128][KST]

    int tid = threadIdx.x;
    int lane = tid & 31, wid = tid >> 5;
    int q0 = blockIdx.x * 128;
    int head = blockIdx.y;
    int split = blockIdx.z;
    const int qoff = HH + head * 64, koff = 2 * HH + head * 64, voff = 3 * HH + head * 64;

    uint32_t qa[8][4];
    {
        int r = q0 + wid * 16 + (lane >> 2);
#pragma unroll
        for (int kt = 0; kt < 8; kt++) {
            int d = kt * 8 + (lane & 3);
            qa[kt][0] = __float_as_uint(comb[(long)r * CC + qoff + d]);
            qa[kt][1] = __float_as_uint(comb[(long)(r + 8) * CC + qoff + d]);
            qa[kt][2] = __float_as_uint(comb[(long)r * CC + qoff + d + 4]);
            qa[kt][3] = __float_as_uint(comb[(long)(r + 8) * CC + qoff + d + 4]);
        }
    }

    float m0 = -1e30f, m1 = -1e30f, l0 = 0.f, l1 = 0.f;
    float o[8][4];
#pragma unroll
    for (int nt = 0; nt < 8; nt++)
#pragma unroll
        for (int r = 0; r < 4; r++) o[nt][r] = 0.f;

    int kbase = split * (NN / SPLITS);
    const int nIter = (NN / SPLITS) / 64;

    auto issue = [&](int it, int buf) {
        int k0 = kbase + it * 64;
#pragma unroll
        for (int j = 0; j < 4; j++) {
            int cc = tid + 256 * j;
            int key = cc >> 4, ch = (cc & 15) * 4;
            cpa16(&Ks[buf * KBUF + key * KST + ch], &comb[(long)(k0 + key) * CC + koff + ch]);
            cpa16(&Vs[buf * VBUF + key * VST + ch], &comb[(long)(k0 + key) * CC + voff + ch]);
        }
    };

    issue(0, 0); CP_COMMIT;
    int cur = 0;
    for (int i = 0; i < nIter; i++) {
        if (i + 1 < nIter) { issue(i + 1, cur ^ 1); CP_COMMIT; cp_wait<1>(); }
        else cp_wait<0>();
        __syncthreads();

        const float* Kc = Ks + cur * KBUF;
        const float* Vc = Vs + cur * VBUF;

        float s[8][4];
#pragma unroll
        for (int nt = 0; nt < 8; nt++)
#pragma unroll
            for (int r = 0; r < 4; r++) s[nt][r] = 0.f;
#pragma unroll
        for (int kt = 0; kt < 8; kt++) {
            int kk = kt * 8 + (lane & 3);
            uint32_t b[2];
#pragma unroll
            for (int nt = 0; nt < 8; nt++) {
                int key = nt * 8 + (lane >> 2);
                b[0] = __float_as_uint(Kc[key * KST + kk]);
                b[1] = __float_as_uint(Kc[key * KST + kk + 4]);
                mma_tf32(s[nt], qa[kt], b);
            }
        }

        float mx0 = -1e30f, mx1 = -1e30f;
#pragma unroll
        for (int nt = 0; nt < 8; nt++) {
            mx0 = fmaxf(mx0, fmaxf(s[nt][0], s[nt][1]));
            mx1 = fmaxf(mx1, fmaxf(s[nt][2], s[nt][3]));
        }
#pragma unroll
        for (int off = 1; off <= 2; off <<= 1) {
            mx0 = fmaxf(mx0, __shfl_xor_sync(0xffffffffu, mx0, off));
            mx1 = fmaxf(mx1, __shfl_xor_sync(0xffffffffu, mx1, off));
        }
        float mn0 = fmaxf(m0, mx0), mn1 = fmaxf(m1, mx1);
        float sum0 = 0.f, sum1 = 0.f;
#pragma unroll
        for (int nt = 0; nt < 8; nt++) {
            s[nt][0] = __expf(s[nt][0] - mn0);
            s[nt][1] = __expf(s[nt][1] - mn0);
            s[nt][2] = __expf(s[nt][2] - mn1);
            s[nt][3] = __expf(s[nt][3] - mn1);
            sum0 += s[nt][0] + s[nt][1];
            sum1 += s[nt][2] + s[nt][3];
        }
#pragma unroll
        for (int off = 1; off <= 2; off <<= 1) {
            sum0 += __shfl_xor_sync(0xffffffffu, sum0, off);
            sum1 += __shfl_xor_sync(0xffffffffu, sum1, off);
        }
        float e0 = __expf(m0 - mn0), e1 = __expf(m1 - mn1);
        l0 = l0 * e0 + sum0;
        l1 = l1 * e1 + sum1;
        m0 = mn0; m1 = mn1;
#pragma unroll
        for (int nt = 0; nt < 8; nt++) {
            o[nt][0] *= e0; o[nt][1] *= e0;
            o[nt][2] *= e1; o[nt][3] *= e1;
        }

        // P into dedicated smem (warp-private rows)
        {
            int r = wid * 16 + (lane >> 2);
#pragma unroll
            for (int nt = 0; nt < 8; nt++) {
                int cb = nt * 8 + 2 * (lane & 3);
                Ps[r * KST + cb]           = __uint_as_float(f2tf(s[nt][0]));
                Ps[r * KST + cb + 1]       = __uint_as_float(f2tf(s[nt][1]));
                Ps[(r + 8) * KST + cb]     = __uint_as_float(f2tf(s[nt][2]));
                Ps[(r + 8) * KST + cb + 1] = __uint_as_float(f2tf(s[nt][3]));
            }
        }
        __syncwarp();

#pragma unroll
        for (int kt = 0; kt < 8; kt++) {
            int r = wid * 16 + (lane >> 2);
            int kk = kt * 8 + (lane & 3);
            uint32_t a[4];
            a[0] = __float_as_uint(Ps[r * KST + kk]);
            a[1] = __float_as_uint(Ps[(r + 8) * KST + kk]);
            a[2] = __float_as_uint(Ps[r * KST + kk + 4]);
            a[3] = __float_as_uint(Ps[(r + 8) * KST + kk + 4]);
            uint32_t b[2];
#pragma unroll
            for (int nt = 0; nt < 8; nt++) {
                int dd = nt * 8 + (lane >> 2);
                b[0] = __float_as_uint(Vc[kk * VST + dd]);
                b[1] = __float_as_uint(Vc[(kk + 4) * VST + dd]);
                mma_tf32(o[nt], a, b);
            }
        }
        __syncthreads();   // K/V readers done before next issue overwrites
        cur ^= 1;
    }

    int r = q0 + wid * 16 + (lane >> 2);
    float* ob = opart + (long)split * NN * HH;
#pragma unroll
    for (int nt = 0; nt < 8; nt++) {
        int cb = head * 64 + nt * 8 + 2 * (lane & 3);
        ob[(long)r * HH + cb]           = o[nt][0];
        ob[(long)r * HH + cb + 1]       = o[nt][1];
        ob[(long)(r + 8) * HH + cb]     = o[nt][2];
        ob[(long)(r + 8) * HH + cb + 1] = o[nt][3];
    }
    if ((lane & 3) == 0) {
        int base = (split * 4 + head) * NN;
        mpart[base + r] = m0;     lpart[base + r] = l0;
        mpart[base + r + 8] = m1; lpart[base + r + 8] = l1;
    }
}

__global__ void flash_merge(const float* __restrict__ opart, const float* __restrict__ mpart,
                            const float* __restrict__ lpart, float* __restrict__ out) {
    int idx = blockIdx.x * blockDim.x + threadIdx.x;
    if (idx >= NN * HH) return;
    int row = idx >> 8, c = idx & 255, head = c >> 6;
    float mv[SPLITS], lv[SPLITS];
    float mmax = -1e30f;
#pragma unroll
    for (int s = 0; s < SPLITS; s++) {
        mv[s] = mpart[(s * 4 + head) * NN + row];
        lv[s] = lpart[(s * 4 + head) * NN + row];
        mmax = fmaxf(mmax, mv[s]);
    }
    float num = 0.f, den = 0.f;
#pragma unroll
    for (int s = 0; s < SPLITS; s++) {
        float w = __expf(mv[s] - mmax);
        num += opart[(long)s * NN * HH + idx] * w;
        den += lv[s] * w;
    }
    out[idx] = num / den;
}

// ---------------- GCN helpers ----------------
__global__ void deg_count(const int* __restrict__ dst, float* deg, int e) {
    int i = blockIdx.x * blockDim.x + threadIdx.x;
    if (i < e) atomicAdd(&deg[dst[i]], 1.f);
}
__global__ void dinv_kernel(const float* __restrict__ deg, float* dinv, int n) {
    int i = blockIdx.x * blockDim.x + threadIdx.x;
    if (i < n) dinv[i] = rsqrtf(deg[i] + 1.f);   // +1 self loop
}

__global__ void gcn_scatter(const int* __restrict__ src, const int* __restrict__ dst,
                            const float* __restrict__ dinv, const float* __restrict__ comb,
                            float* __restrict__ outb, int e) {
    int w = (blockIdx.x * blockDim.x + threadIdx.x) >> 5;
    int lane = threadIdx.x & 31;
    if (w >= e) return;
    int s = src[w], d = dst[w];
    float coef = dinv[s] * dinv[d];
    const float4* xs = (const float4*)(comb + (long)s * CC);
    float* ad = outb + (long)d * HH;
    float4 v0 = xs[lane];
    float4 v1 = xs[lane + 32];
    red4(ad + lane * 4,       v0.x * coef, v0.y * coef, v0.z * coef, v0.w * coef);
    red4(ad + 128 + lane * 4, v1.x * coef, v1.y * coef, v1.z * coef, v1.w * coef);
}

__global__ void combine2(float* __restrict__ outb, const float* __restrict__ comb,
                         const float* __restrict__ dinv, const float* __restrict__ gcn_b,
                         int total) {
    int idx = blockIdx.x * blockDim.x + threadIdx.x;
    if (idx >= total) return;
    int i = idx >> 8, c = idx & 255;
    float dv = dinv[i];
    outb[idx] += comb[(long)i * CC + c] * dv * dv + gcn_b[c];
}

// ---------------- launch ----------------
extern "C" void kernel_launch(void* const* d_in, const int* in_sizes, int n_in,
                              void* d_out, int out_size) {
    const float* x      = (const float*)d_in[0];
    const int*   ei     = (const int*)d_in[1];
    const float* pre_w  = (const float*)d_in[2];
    const float* pre_b  = (const float*)d_in[3];
    const float* mlp_w1 = (const float*)d_in[24];
    const float* mlp_b1 = (const float*)d_in[25];
    const float* mlp_w2 = (const float*)d_in[26];
    const float* mlp_b2 = (const float*)d_in[27];

    float *h, *comb, *attn, *outb, *ffn, *hid, *deg, *dinv;
    float *opart, *mpart, *lpart;
    cudaGetSymbolAddress((void**)&h,    g_h);
    cudaGetSymbolAddress((void**)&comb, g_comb);
    cudaGetSymbolAddress((void**)&attn, g_attn);
    cudaGetSymbolAddress((void**)&outb, g_out);
    cudaGetSymbolAddress((void**)&ffn,  g_ffn);
    cudaGetSymbolAddress((void**)&hid,  g_hid);
    cudaGetSymbolAddress((void**)&deg,  g_deg);
    cudaGetSymbolAddress((void**)&dinv, g_dinv);
    cudaGetSymbolAddress((void**)&opart, g_opart);
    cudaGetSymbolAddress((void**)&mpart, g_mpart);
    cudaGetSymbolAddress((void**)&lpart, g_lpart);

    const int flash_smem = (2 * KBUF + 2 * VBUF + 128 * KST) * (int)sizeof(float);  // 106496
    cudaFuncSetAttribute(flash_part, cudaFuncAttributeMaxDynamicSharedMemorySize, flash_smem);
    const int sym_smem = 4 * 3 * 64 * 20 * (int)sizeof(float);  // 61440
    cudaFuncSetAttribute(mlp2_sym, cudaFuncAttributeMaxDynamicSharedMemorySize, sym_smem);

    const int BIG = 1 << 30;

    cudaMemsetAsync(deg, 0, NN * sizeof(float));
    deg_count<<<(EE + 255) / 256, 256>>>(ei + EE, deg, EE);
    dinv_kernel<<<(NN + 255) / 256, 256>>>(deg, dinv, NN);

    // pre: h = relu(x @ pre_w^T + pre_b)
    tgemm<<<dim3(HH / 64, NN / 64), 128>>>(x, pre_w, pre_w, BIG, pre_b, nullptr,
                                           nullptr, 0.f, h, NN, HH, 128, 1, 0);

    for (int L = 0; L < 2; L++) {
        int base = 4 + L * 10;
        const float* gcn_w  = (const float*)d_in[base + 0];
        const float* gcn_b  = (const float*)d_in[base + 1];
        const float* in_w   = (const float*)d_in[base + 2];
        const float* in_b   = (const float*)d_in[base + 3];
        const float* out_w  = (const float*)d_in[base + 4];
        const float* out_b  = (const float*)d_in[base + 5];
        const float* ffn_w1 = (const float*)d_in[base + 6];
        const float* ffn_b1 = (const float*)d_in[base + 7];
        const float* ffn_w2 = (const float*)d_in[base + 8];
        const float* ffn_b2 = (const float*)d_in[base + 9];

        tgemm<<<dim3(CC / 64, NN / 64), 128>>>(h, gcn_w, in_w, HH, nullptr, in_b,
                                               nullptr, 0.f, comb, NN, CC, HH, 0, 2);
        flash_part<<<dim3(NN / 128, 4, SPLITS), 256, flash_smem>>>(comb, opart, mpart, lpart);
        flash_merge<<<(NN * HH) / 256, 256>>>(opart, mpart, lpart, attn);
        tgemm<<<dim3(HH / 64, NN / 64), 128>>>(attn, out_w, out_w, BIG, out_b, nullptr,
                                               h, 2.f, outb, NN, HH, HH, 0, 0);
        gcn_scatter<<<(EE * 32) / 256, 256>>>(ei, ei + EE, dinv, comb, outb, EE);
        combine2<<<(NN * HH) / 256, 256>>>(outb, comb, dinv, gcn_b, NN * HH);
        tgemm<<<dim3(2 * HH / 64, NN / 64), 128>>>(outb, ffn_w1, ffn_w1, BIG, ffn_b1, nullptr,
                                                   nullptr, 0.f, ffn, NN, 2 * HH, HH, 1, 0);
        tgemm<<<dim3(HH / 64, NN / 64), 128>>>(ffn, ffn_w2, ffn_w2, BIG, ffn_b2, nullptr,
                                               outb, 1.f, h, NN, HH, 2 * HH, 1, 0);
    }

    // head: mlp1 then fused mlp2+symmetrize
    tgemm<<<dim3(HH / 64, NN / 64), 128>>>(h, mlp_w1, mlp_w1, BIG, mlp_b1, nullptr,
                                           nullptr, 0.f, hid, NN, HH, HH, 1, 0);
    mlp2_sym<<<dim3(NN / 64, NN / 64), 128, sym_smem>>>(hid, mlp_w2, mlp_b2, (float*)d_out);
}

// round 12
// speedup vs baseline: 1.1041x; 1.0006x over previous
#include <cuda_runtime.h>
#include <cuda_bf16.h>
#include <stdint.h>
#include <math.h>

#define NN 4096
#define HH 256
#define EE 65536
#define SPLITS 8
#define CC 1024

// ---------------- device scratch ----------------
__device__ float g_h[NN * HH];
__device__ float g_comb[NN * CC];
__device__ float g_attn[NN * HH];
__device__ float g_out[NN * HH];
__device__ float g_ffn[NN * 2 * HH];
__device__ float g_hid[NN * HH];
__device__ float g_deg[NN];
__device__ float g_dinv[NN];
__device__ float g_opart[SPLITS * NN * HH];
__device__ float g_mpart[SPLITS * 4 * NN];
__device__ float g_lpart[SPLITS * 4 * NN];

// ---------------- helpers ----------------
__device__ __forceinline__ uint32_t f2tf(float f) {
    uint32_t u;
    asm("cvt.rna.tf32.f32 %0, %1;" : "=r"(u) : "f"(f));
    return u;
}

__device__ __forceinline__ void mma_tf32(float c[4], const uint32_t a[4], const uint32_t b[2]) {
    asm volatile(
        "mma.sync.aligned.m16n8k8.row.col.f32.tf32.tf32.f32 "
        "{%0,%1,%2,%3},{%4,%5,%6,%7},{%8,%9},{%0,%1,%2,%3};\n"
        : "+f"(c[0]), "+f"(c[1]), "+f"(c[2]), "+f"(c[3])
        : "r"(a[0]), "r"(a[1]), "r"(a[2]), "r"(a[3]), "r"(b[0]), "r"(b[1]));
}

__device__ __forceinline__ void cpa16(void* s, const void* g) {
    uint32_t sa = (uint32_t)__cvta_generic_to_shared(s);
    asm volatile("cp.async.cg.shared.global [%0], [%1], 16;\n" :: "r"(sa), "l"(g) : "memory");
}
#define CP_COMMIT asm volatile("cp.async.commit_group;\n" ::: "memory")
template<int W> __device__ __forceinline__ void cp_wait() {
    asm volatile("cp.async.wait_group %0;\n" :: "n"(W) : "memory");
}

__device__ __forceinline__ void red4(float* addr, float a, float b, float c, float d) {
    asm volatile("red.global.add.v4.f32 [%0], {%1,%2,%3,%4};"
                 :: "l"(addr), "f"(a), "f"(b), "f"(c), "f"(d) : "memory");
}

#define GBK 16

// ---------------- TF32 GEMM: 64x64, 4 warps (32x32), 3-stage -- for N=256 GEMMs ----------------
__global__ void __launch_bounds__(128) tgemm(
    const float* __restrict__ A, const float* __restrict__ W, const float* __restrict__ W2,
    int wsplit, const float* __restrict__ bias, const float* __restrict__ bias2,
    const float* __restrict__ add, float addscale,
    float* __restrict__ C, int M, int Nn, int K, int relu, int outmode) {
    __shared__ float As[3][64][20];
    __shared__ float Ws[3][64][20];

    int tid = threadIdx.x;
    int lane = tid & 31, wid = tid >> 5;
    int warp_m = wid & 1, warp_n = wid >> 1;
    int m0 = blockIdx.y * 64, n0 = blockIdx.x * 64;

    const float* Wb;
    const float* bb;
    int bshift;
    if (n0 < wsplit) { Wb = W  + (long)n0 * K;            bb = bias;  bshift = 0; }
    else             { Wb = W2 + (long)(n0 - wsplit) * K; bb = bias2; bshift = wsplit; }

    float c[2][4][4];
#pragma unroll
    for (int mt = 0; mt < 2; mt++)
#pragma unroll
        for (int nt = 0; nt < 4; nt++)
#pragma unroll
            for (int r = 0; r < 4; r++) c[mt][nt][r] = 0.f;

    int nIter = K / GBK;

    auto issue = [&](int it, int buf) {
        int k0 = it * GBK;
#pragma unroll
        for (int j = 0; j < 2; j++) {
            int cc = tid + 128 * j;
            int row = cc >> 2, ch = (cc & 3) * 4;
            cpa16(&As[buf][row][ch], &A[(long)(m0 + row) * K + k0 + ch]);
            cpa16(&Ws[buf][row][ch], &Wb[(long)row * K + k0 + ch]);
        }
    };

    issue(0, 0); CP_COMMIT;
    issue(1, 1); CP_COMMIT;

    for (int i = 0; i < nIter; i++) {
        int buf = i % 3;
        if (i + 2 < nIter) { issue(i + 2, (i + 2) % 3); CP_COMMIT; cp_wait<2>(); }
        else if (i + 1 < nIter) cp_wait<1>();
        else cp_wait<0>();
        __syncthreads();

#pragma unroll
        for (int ks = 0; ks < GBK; ks += 8) {
            uint32_t a[2][4], b[4][2];
            int kk = ks + (lane & 3);
#pragma unroll
            for (int mt = 0; mt < 2; mt++) {
                int row = warp_m * 32 + mt * 16 + (lane >> 2);
                a[mt][0] = f2tf(As[buf][row][kk]);
                a[mt][1] = f2tf(As[buf][row + 8][kk]);
                a[mt][2] = f2tf(As[buf][row][kk + 4]);
                a[mt][3] = f2tf(As[buf][row + 8][kk + 4]);
            }
#pragma unroll
            for (int nt = 0; nt < 4; nt++) {
                int nc = warp_n * 32 + nt * 8 + (lane >> 2);
                b[nt][0] = f2tf(Ws[buf][nc][kk]);
                b[nt][1] = f2tf(Ws[buf][nc][kk + 4]);
            }
#pragma unroll
            for (int mt = 0; mt < 2; mt++)
#pragma unroll
                for (int nt = 0; nt < 4; nt++) mma_tf32(c[mt][nt], a[mt], b[nt]);
        }
        __syncthreads();
    }

#pragma unroll
    for (int mt = 0; mt < 2; mt++) {
        int rb = m0 + warp_m * 32 + mt * 16 + (lane >> 2);
#pragma unroll
        for (int nt = 0; nt < 4; nt++) {
            int cb = n0 + warp_n * 32 + nt * 8 + 2 * (lane & 3);
#pragma unroll
            for (int r = 0; r < 4; r++) {
                int mm = rb + (r >> 1) * 8;
                int nn = cb + (r & 1);
                float v = c[mt][nt][r];
                if (bb)  v += bb[nn - bshift];
                if (add) v += addscale * add[(long)mm * HH + nn];
                if (relu) v = fmaxf(v, 0.f);
                if (outmode == 0) C[(long)mm * Nn + nn] = v;
                else              C[(long)mm * Nn + nn] = __uint_as_float(f2tf(v));
            }
        }
    }
}

// ---------------- TF32 GEMM wide: 64x128 block, warp tile 32x64 -- for N>=512 GEMMs ----------------
__global__ void __launch_bounds__(128) tgemm_wide(
    const float* __restrict__ A, const float* __restrict__ W, const float* __restrict__ W2,
    int wsplit, const float* __restrict__ bias, const float* __restrict__ bias2,
    float* __restrict__ C, int M, int Nn, int K, int relu, int outmode) {
    __shared__ float As[3][64][20];
    __shared__ float Ws[3][128][20];

    int tid = threadIdx.x;
    int lane = tid & 31, wid = tid >> 5;
    int warp_m = wid & 1, warp_n = wid >> 1;
    int m0 = blockIdx.y * 64, n0 = blockIdx.x * 128;

    const float* Wb;
    const float* bb;
    int bshift;
    if (n0 < wsplit) { Wb = W  + (long)n0 * K;            bb = bias;  bshift = 0; }
    else             { Wb = W2 + (long)(n0 - wsplit) * K; bb = bias2; bshift = wsplit; }

    float c[2][8][4];
#pragma unroll
    for (int mt = 0; mt < 2; mt++)
#pragma unroll
        for (int nt = 0; nt < 8; nt++)
#pragma unroll
            for (int r = 0; r < 4; r++) c[mt][nt][r] = 0.f;

    int nIter = K / GBK;

    auto issue = [&](int it, int buf) {
        int k0 = it * GBK;
#pragma unroll
        for (int j = 0; j < 2; j++) {
            int cc = tid + 128 * j;
            int row = cc >> 2, ch = (cc & 3) * 4;
            cpa16(&As[buf][row][ch], &A[(long)(m0 + row) * K + k0 + ch]);
        }
#pragma unroll
        for (int j = 0; j < 4; j++) {
            int cc = tid + 128 * j;
            int row = cc >> 2, ch = (cc & 3) * 4;
            cpa16(&Ws[buf][row][ch], &Wb[(long)row * K + k0 + ch]);
        }
    };

    issue(0, 0); CP_COMMIT;
    issue(1, 1); CP_COMMIT;

    for (int i = 0; i < nIter; i++) {
        int buf = i % 3;
        if (i + 2 < nIter) { issue(i + 2, (i + 2) % 3); CP_COMMIT; cp_wait<2>(); }
        else if (i + 1 < nIter) cp_wait<1>();
        else cp_wait<0>();
        __syncthreads();

#pragma unroll
        for (int ks = 0; ks < GBK; ks += 8) {
            uint32_t a[2][4], b[8][2];
            int kk = ks + (lane & 3);
#pragma unroll
            for (int mt = 0; mt < 2; mt++) {
                int row = warp_m * 32 + mt * 16 + (lane >> 2);
                a[mt][0] = f2tf(As[buf][row][kk]);
                a[mt][1] = f2tf(As[buf][row + 8][kk]);
                a[mt][2] = f2tf(As[buf][row][kk + 4]);
                a[mt][3] = f2tf(As[buf][row + 8][kk + 4]);
            }
#pragma unroll
            for (int nt = 0; nt < 8; nt++) {
                int nc = warp_n * 64 + nt * 8 + (lane >> 2);
                b[nt][0] = f2tf(Ws[buf][nc][kk]);
                b[nt][1] = f2tf(Ws[buf][nc][kk + 4]);
            }
#pragma unroll
            for (int mt = 0; mt < 2; mt++)
#pragma unroll
                for (int nt = 0; nt < 8; nt++) mma_tf32(c[mt][nt], a[mt], b[nt]);
        }
        __syncthreads();
    }

#pragma unroll
    for (int mt = 0; mt < 2; mt++) {
        int rb = m0 + warp_m * 32 + mt * 16 + (lane >> 2);
#pragma unroll
        for (int nt = 0; nt < 8; nt++) {
            int cb = n0 + warp_n * 64 + nt * 8 + 2 * (lane & 3);
#pragma unroll
            for (int r = 0; r < 4; r++) {
                int mm = rb + (r >> 1) * 8;
                int nn = cb + (r & 1);
                float v = c[mt][nt][r];
                if (bb)  v += bb[nn - bshift];
                if (relu) v = fmaxf(v, 0.f);
                if (outmode == 0) {
                    C[(long)mm * Nn + nn] = v;
                } else {   // comb layout
                    if (nn < HH)          C[(long)mm * Nn + nn] = v;
                    else {
                        if (nn < 2 * HH) v *= 0.125f;
                        C[(long)mm * Nn + nn] = __uint_as_float(f2tf(v));
                    }
                }
            }
        }
    }
}

// ---------------- head GEMM + symmetrize, warp-split ----------------
// warps 0-1: c1 = Hi@Wj^T (32x64 each); warps 2-3: c2 = Hj@Wi^T.
// out_ij = 0.5*(c1 + b[n] + c2^T + b[m]); out_ji = out_ij^T.
#define TRST 68

__global__ void __launch_bounds__(128) mlp2_sym(
    const float* __restrict__ A, const float* __restrict__ W,
    const float* __restrict__ bias, float* __restrict__ C) {
    int ti = blockIdx.y, tj = blockIdx.x;
    if (tj < ti) return;
    extern __shared__ float sm[];
    float* Hi = sm;            // [3][64][20] each
    float* Hj = sm + 3840;
    float* Wj = sm + 7680;
    float* Wi = sm + 11520;

    int tid = threadIdx.x;
    int lane = tid & 31, wid = tid >> 5;
    int matsel = wid >> 1;     // 0: c1, 1: c2
    int warp_m = wid & 1;
    int mi0 = ti * 64, mj0 = tj * 64;

    float c[2][8][4];
#pragma unroll
    for (int mt = 0; mt < 2; mt++)
#pragma unroll
        for (int nt = 0; nt < 8; nt++)
#pragma unroll
            for (int r = 0; r < 4; r++) c[mt][nt][r] = 0.f;

    const int nIter = HH / GBK;   // 16

    auto issue = [&](int it, int buf) {
        int k0 = it * GBK;
        long bb = (long)buf * 1280;
#pragma unroll
        for (int j = 0; j < 2; j++) {
            int cc = tid + 128 * j;
            int row = cc >> 2, ch = (cc & 3) * 4;
            long so = bb + row * 20 + ch;
            cpa16(&Hi[so], &A[(long)(mi0 + row) * HH + k0 + ch]);
            cpa16(&Hj[so], &A[(long)(mj0 + row) * HH + k0 + ch]);
            cpa16(&Wj[so], &W[(long)(mj0 + row) * HH + k0 + ch]);
            cpa16(&Wi[so], &W[(long)(mi0 + row) * HH + k0 + ch]);
        }
    };

    issue(0, 0); CP_COMMIT;
    issue(1, 1); CP_COMMIT;

    const float* Asel = matsel ? Hj : Hi;
    const float* Bsel = matsel ? Wi : Wj;

    for (int i = 0; i < nIter; i++) {
        int buf = i % 3;
        if (i + 2 < nIter) { issue(i + 2, (i + 2) % 3); CP_COMMIT; cp_wait<2>(); }
        else if (i + 1 < nIter) cp_wait<1>();
        else cp_wait<0>();
        __syncthreads();

        long bb = (long)buf * 1280;
#pragma unroll
        for (int ks = 0; ks < GBK; ks += 8) {
            uint32_t a[2][4], b[8][2];
            int kk = ks + (lane & 3);
#pragma unroll
            for (int mt = 0; mt < 2; mt++) {
                int row = warp_m * 32 + mt * 16 + (lane >> 2);
                long o0 = bb + row * 20 + kk, o1 = bb + (row + 8) * 20 + kk;
                a[mt][0] = f2tf(Asel[o0]);     a[mt][1] = f2tf(Asel[o1]);
                a[mt][2] = f2tf(Asel[o0 + 4]); a[mt][3] = f2tf(Asel[o1 + 4]);
            }
#pragma unroll
            for (int nt = 0; nt < 8; nt++) {
                int nc = nt * 8 + (lane >> 2);
                long o = bb + nc * 20 + kk;
                b[nt][0] = f2tf(Bsel[o]); b[nt][1] = f2tf(Bsel[o + 4]);
            }
#pragma unroll
            for (int mt = 0; mt < 2; mt++)
#pragma unroll
                for (int nt = 0; nt < 8; nt++) mma_tf32(c[mt][nt], a[mt], b[nt]);
        }
        __syncthreads();   // also protects smem reuse by epilogue
    }

    // epilogue: c1 -> Cs, c2 -> Tr; block-wide symmetrize
    float* Cs  = sm;                  // [64][TRST]
    float* Tr  = sm + 64 * TRST;      // [64][TRST]
    float* Tr2 = sm + 2 * 64 * TRST;  // [64][TRST]
    float* dstbuf = matsel ? Tr : Cs;

#pragma unroll
    for (int mt = 0; mt < 2; mt++) {
        int rb = warp_m * 32 + mt * 16 + (lane >> 2);
#pragma unroll
        for (int nt = 0; nt < 8; nt++) {
            int cb = nt * 8 + 2 * (lane & 3);
#pragma unroll
            for (int r = 0; r < 4; r++)
                dstbuf[(rb + (r >> 1) * 8) * TRST + cb + (r & 1)] = c[mt][nt][r];
        }
    }
    __syncthreads();

    {
        int r = tid >> 1, half = tid & 1;
        float bi = bias[mi0 + r];
        int cbase = half * 32;
#pragma unroll
        for (int j = 0; j < 32; j += 4) {
            int cc = cbase + j;
            float4 v;
            v.x = 0.5f * (Cs[r * TRST + cc]     + bias[mj0 + cc]     + Tr[(cc)     * TRST + r] + bi);
            v.y = 0.5f * (Cs[r * TRST + cc + 1] + bias[mj0 + cc + 1] + Tr[(cc + 1) * TRST + r] + bi);
            v.z = 0.5f * (Cs[r * TRST + cc + 2] + bias[mj0 + cc + 2] + Tr[(cc + 2) * TRST + r] + bi);
            v.w = 0.5f * (Cs[r * TRST + cc + 3] + bias[mj0 + cc + 3] + Tr[(cc + 3) * TRST + r] + bi);
            *(float4*)&C[(long)(mi0 + r) * NN + mj0 + cc] = v;
            Tr2[(cc)     * TRST + r] = v.x;
            Tr2[(cc + 1) * TRST + r] = v.y;
            Tr2[(cc + 2) * TRST + r] = v.z;
            Tr2[(cc + 3) * TRST + r] = v.w;
        }
    }

    if (ti != tj) {
        __syncthreads();
        int row = tid >> 1, half = tid & 1;
        long base = (long)(mj0 + row) * NN + mi0 + half * 32;
        const float* tr = Tr2 + row * TRST + half * 32;
#pragma unroll
        for (int k = 0; k < 32; k += 4)
            *(float4*)&C[base + k] = *(const float4*)&tr[k];
    }
}

// ---------------- TF32 flash attention: BM=128, 256 thr, dedicated P ----------------
#define KST 68
#define VST 72
#define KBUF (64 * KST)
#define VBUF (64 * VST)

__global__ void __launch_bounds__(256) flash_part(const float* __restrict__ comb,
                                                  float* __restrict__ opart,
                                                  float* __restrict__ mpart,
                                                  float* __restrict__ lpart) {
    extern __shared__ float sm[];
    float* Ks = sm;
    float* Vs = sm + 2 * KBUF;
    float* Ps = sm + 2 * KBUF + 2 * VBUF;

    int tid = threadIdx.x;
    int lane = tid & 31, wid = tid >> 5;
    int q0 = blockIdx.x * 128;
    int head = blockIdx.y;
    int split = blockIdx.z;
    const int qoff = HH + head * 64, koff = 2 * HH + head * 64, voff = 3 * HH + head * 64;

    uint32_t qa[8][4];
    {
        int r = q0 + wid * 16 + (lane >> 2);
#pragma unroll
        for (int kt = 0; kt < 8; kt++) {
            int d = kt * 8 + (lane & 3);
            qa[kt][0] = __float_as_uint(comb[(long)r * CC + qoff + d]);
            qa[kt][1] = __float_as_uint(comb[(long)(r + 8) * CC + qoff + d]);
            qa[kt][2] = __float_as_uint(comb[(long)r * CC + qoff + d + 4]);
            qa[kt][3] = __float_as_uint(comb[(long)(r + 8) * CC + qoff + d + 4]);
        }
    }

    float m0 = -1e30f, m1 = -1e30f, l0 = 0.f, l1 = 0.f;
    float o[8][4];
#pragma unroll
    for (int nt = 0; nt < 8; nt++)
#pragma unroll
        for (int r = 0; r < 4; r++) o[nt][r] = 0.f;

    int kbase = split * (NN / SPLITS);
    const int nIter = (NN / SPLITS) / 64;

    auto issue = [&](int it, int buf) {
        int k0 = kbase + it * 64;
#pragma unroll
        for (int j = 0; j < 4; j++) {
            int cc = tid + 256 * j;
            int key = cc >> 4, ch = (cc & 15) * 4;
            cpa16(&Ks[buf * KBUF + key * KST + ch], &comb[(long)(k0 + key) * CC + koff + ch]);
            cpa16(&Vs[buf * VBUF + key * VST + ch], &comb[(long)(k0 + key) * CC + voff + ch]);
        }
    };

    issue(0, 0); CP_COMMIT;
    int cur = 0;
    for (int i = 0; i < nIter; i++) {
        if (i + 1 < nIter) { issue(i + 1, cur ^ 1); CP_COMMIT; cp_wait<1>(); }
        else cp_wait<0>();
        __syncthreads();

        const float* Kc = Ks + cur * KBUF;
        const float* Vc = Vs + cur * VBUF;

        float s[8][4];
#pragma unroll
        for (int nt = 0; nt < 8; nt++)
#pragma unroll
            for (int r = 0; r < 4; r++) s[nt][r] = 0.f;
#pragma unroll
        for (int kt = 0; kt < 8; kt++) {
            int kk = kt * 8 + (lane & 3);
            uint32_t b[2];
#pragma unroll
            for (int nt = 0; nt < 8; nt++) {
                int key = nt * 8 + (lane >> 2);
                b[0] = __float_as_uint(Kc[key * KST + kk]);
                b[1] = __float_as_uint(Kc[key * KST + kk + 4]);
                mma_tf32(s[nt], qa[kt], b);
            }
        }

        float mx0 = -1e30f, mx1 = -1e30f;
#pragma unroll
        for (int nt = 0; nt < 8; nt++) {
            mx0 = fmaxf(mx0, fmaxf(s[nt][0], s[nt][1]));
            mx1 = fmaxf(mx1, fmaxf(s[nt][2], s[nt][3]));
        }
#pragma unroll
        for (int off = 1; off <= 2; off <<= 1) {
            mx0 = fmaxf(mx0, __shfl_xor_sync(0xffffffffu, mx0, off));
            mx1 = fmaxf(mx1, __shfl_xor_sync(0xffffffffu, mx1, off));
        }
        float mn0 = fmaxf(m0, mx0), mn1 = fmaxf(m1, mx1);
        float sum0 = 0.f, sum1 = 0.f;
#pragma unroll
        for (int nt = 0; nt < 8; nt++) {
            s[nt][0] = __expf(s[nt][0] - mn0);
            s[nt][1] = __expf(s[nt][1] - mn0);
            s[nt][2] = __expf(s[nt][2] - mn1);
            s[nt][3] = __expf(s[nt][3] - mn1);
            sum0 += s[nt][0] + s[nt][1];
            sum1 += s[nt][2] + s[nt][3];
        }
#pragma unroll
        for (int off = 1; off <= 2; off <<= 1) {
            sum0 += __shfl_xor_sync(0xffffffffu, sum0, off);
            sum1 += __shfl_xor_sync(0xffffffffu, sum1, off);
        }
        float e0 = __expf(m0 - mn0), e1 = __expf(m1 - mn1);
        l0 = l0 * e0 + sum0;
        l1 = l1 * e1 + sum1;
        m0 = mn0; m1 = mn1;
#pragma unroll
        for (int nt = 0; nt < 8; nt++) {
            o[nt][0] *= e0; o[nt][1] *= e0;
            o[nt][2] *= e1; o[nt][3] *= e1;
        }

        {
            int r = wid * 16 + (lane >> 2);
#pragma unroll
            for (int nt = 0; nt < 8; nt++) {
                int cb = nt * 8 + 2 * (lane & 3);
                Ps[r * KST + cb]           = __uint_as_float(f2tf(s[nt][0]));
                Ps[r * KST + cb + 1]       = __uint_as_float(f2tf(s[nt][1]));
                Ps[(r + 8) * KST + cb]     = __uint_as_float(f2tf(s[nt][2]));
                Ps[(r + 8) * KST + cb + 1] = __uint_as_float(f2tf(s[nt][3]));
            }
        }
        __syncwarp();

#pragma unroll
        for (int kt = 0; kt < 8; kt++) {
            int r = wid * 16 + (lane >> 2);
            int kk = kt * 8 + (lane & 3);
            uint32_t a[4];
            a[0] = __float_as_uint(Ps[r * KST + kk]);
            a[1] = __float_as_uint(Ps[(r + 8) * KST + kk]);
            a[2] = __float_as_uint(Ps[r * KST + kk + 4]);
            a[3] = __float_as_uint(Ps[(r + 8) * KST + kk + 4]);
            uint32_t b[2];
#pragma unroll
            for (int nt = 0; nt < 8; nt++) {
                int dd = nt * 8 + (lane >> 2);
                b[0] = __float_as_uint(Vc[kk * VST + dd]);
                b[1] = __float_as_uint(Vc[(kk + 4) * VST + dd]);
                mma_tf32(o[nt], a, b);
            }
        }
        __syncthreads();
        cur ^= 1;
    }

    int r = q0 + wid * 16 + (lane >> 2);
    float* ob = opart + (long)split * NN * HH;
#pragma unroll
    for (int nt = 0; nt < 8; nt++) {
        int cb = head * 64 + nt * 8 + 2 * (lane & 3);
        ob[(long)r * HH + cb]           = o[nt][0];
        ob[(long)r * HH + cb + 1]       = o[nt][1];
        ob[(long)(r + 8) * HH + cb]     = o[nt][2];
        ob[(long)(r + 8) * HH + cb + 1] = o[nt][3];
    }
    if ((lane & 3) == 0) {
        int base = (split * 4 + head) * NN;
        mpart[base + r] = m0;     lpart[base + r] = l0;
        mpart[base + r + 8] = m1; lpart[base + r + 8] = l1;
    }
}

__global__ void flash_merge(const float* __restrict__ opart, const float* __restrict__ mpart,
                            const float* __restrict__ lpart, float* __restrict__ out) {
    int idx = blockIdx.x * blockDim.x + threadIdx.x;
    if (idx >= NN * HH) return;
    int row = idx >> 8, c = idx & 255, head = c >> 6;
    float mv[SPLITS], lv[SPLITS];
    float mmax = -1e30f;
#pragma unroll
    for (int s = 0; s < SPLITS; s++) {
        mv[s] = mpart[(s * 4 + head) * NN + row];
        lv[s] = lpart[(s * 4 + head) * NN + row];
        mmax = fmaxf(mmax, mv[s]);
    }
    float num = 0.f, den = 0.f;
#pragma unroll
    for (int s = 0; s < SPLITS; s++) {
        float w = __expf(mv[s] - mmax);
        num += opart[(long)s * NN * HH + idx] * w;
        den += lv[s] * w;
    }
    out[idx] = num / den;
}

// ---------------- GCN helpers ----------------
__global__ void deg_count(const int* __restrict__ dst, float* deg, int e) {
    int i = blockIdx.x * blockDim.x + threadIdx.x;
    if (i < e) atomicAdd(&deg[dst[i]], 1.f);
}
__global__ void dinv_kernel(const float* __restrict__ deg, float* dinv, int n) {
    int i = blockIdx.x * blockDim.x + threadIdx.x;
    if (i < n) dinv[i] = rsqrtf(deg[i] + 1.f);
}

__global__ void gcn_scatter(const int* __restrict__ src, const int* __restrict__ dst,
                            const float* __restrict__ dinv, const float* __restrict__ comb,
                            float* __restrict__ outb, int e) {
    int w = (blockIdx.x * blockDim.x + threadIdx.x) >> 5;
    int lane = threadIdx.x & 31;
    if (w >= e) return;
    int s = src[w], d = dst[w];
    float coef = dinv[s] * dinv[d];
    const float4* xs = (const float4*)(comb + (long)s * CC);
    float* ad = outb + (long)d * HH;
    float4 v0 = xs[lane];
    float4 v1 = xs[lane + 32];
    red4(ad + lane * 4,       v0.x * coef, v0.y * coef, v0.z * coef, v0.w * coef);
    red4(ad + 128 + lane * 4, v1.x * coef, v1.y * coef, v1.z * coef, v1.w * coef);
}

__global__ void combine2(float* __restrict__ outb, const float* __restrict__ comb,
                         const float* __restrict__ dinv, const float* __restrict__ gcn_b,
                         int total) {
    int idx = blockIdx.x * blockDim.x + threadIdx.x;
    if (idx >= total) return;
    int i = idx >> 8, c = idx & 255;
    float dv = dinv[i];
    outb[idx] += comb[(long)i * CC + c] * dv * dv + gcn_b[c];
}

// ---------------- launch ----------------
extern "C" void kernel_launch(void* const* d_in, const int* in_sizes, int n_in,
                              void* d_out, int out_size) {
    const float* x      = (const float*)d_in[0];
    const int*   ei     = (const int*)d_in[1];
    const float* pre_w  = (const float*)d_in[2];
    const float* pre_b  = (const float*)d_in[3];
    const float* mlp_w1 = (const float*)d_in[24];
    const float* mlp_b1 = (const float*)d_in[25];
    const float* mlp_w2 = (const float*)d_in[26];
    const float* mlp_b2 = (const float*)d_in[27];

    float *h, *comb, *attn, *outb, *ffn, *hid, *deg, *dinv;
    float *opart, *mpart, *lpart;
    cudaGetSymbolAddress((void**)&h,    g_h);
    cudaGetSymbolAddress((void**)&comb, g_comb);
    cudaGetSymbolAddress((void**)&attn, g_attn);
    cudaGetSymbolAddress((void**)&outb, g_out);
    cudaGetSymbolAddress((void**)&ffn,  g_ffn);
    cudaGetSymbolAddress((void**)&hid,  g_hid);
    cudaGetSymbolAddress((void**)&deg,  g_deg);
    cudaGetSymbolAddress((void**)&dinv, g_dinv);
    cudaGetSymbolAddress((void**)&opart, g_opart);
    cudaGetSymbolAddress((void**)&mpart, g_mpart);
    cudaGetSymbolAddress((void**)&lpart, g_lpart);

    const int flash_smem = (2 * KBUF + 2 * VBUF + 128 * KST) * (int)sizeof(float);  // 106496
    cudaFuncSetAttribute(flash_part, cudaFuncAttributeMaxDynamicSharedMemorySize, flash_smem);
    const int sym_smem = 4 * 3 * 64 * 20 * (int)sizeof(float);  // 61440 (>= 3*64*68*4 epilogue)
    cudaFuncSetAttribute(mlp2_sym, cudaFuncAttributeMaxDynamicSharedMemorySize, sym_smem);

    const int BIG = 1 << 30;

    cudaMemsetAsync(deg, 0, NN * sizeof(float));
    deg_count<<<(EE + 255) / 256, 256>>>(ei + EE, deg, EE);
    dinv_kernel<<<(NN + 255) / 256, 256>>>(deg, dinv, NN);

    // pre: h = relu(x @ pre_w^T + pre_b)
    tgemm<<<dim3(HH / 64, NN / 64), 128>>>(x, pre_w, pre_w, BIG, pre_b, nullptr,
                                           nullptr, 0.f, h, NN, HH, 128, 1, 0);

    for (int L = 0; L < 2; L++) {
        int base = 4 + L * 10;
        const float* gcn_w  = (const float*)d_in[base + 0];
        const float* gcn_b  = (const float*)d_in[base + 1];
        const float* in_w   = (const float*)d_in[base + 2];
        const float* in_b   = (const float*)d_in[base + 3];
        const float* out_w  = (const float*)d_in[base + 4];
        const float* out_b  = (const float*)d_in[base + 5];
        const float* ffn_w1 = (const float*)d_in[base + 6];
        const float* ffn_b1 = (const float*)d_in[base + 7];
        const float* ffn_w2 = (const float*)d_in[base + 8];
        const float* ffn_b2 = (const float*)d_in[base + 9];

        // fused xlin|qkv GEMM (wide tiles)
        tgemm_wide<<<dim3(CC / 128, NN / 64), 128>>>(h, gcn_w, in_w, HH, nullptr, in_b,
                                                     comb, NN, CC, HH, 0, 2);
        flash_part<<<dim3(NN / 128, 4, SPLITS), 256, flash_smem>>>(comb, opart, mpart, lpart);
        flash_merge<<<(NN * HH) / 256, 256>>>(opart, mpart, lpart, attn);
        tgemm<<<dim3(HH / 64, NN / 64), 128>>>(attn, out_w, out_w, BIG, out_b, nullptr,
                                               h, 2.f, outb, NN, HH, HH, 0, 0);
        gcn_scatter<<<(EE * 32) / 256, 256>>>(ei, ei + EE, dinv, comb, outb, EE);
        combine2<<<(NN * HH) / 256, 256>>>(outb, comb, dinv, gcn_b, NN * HH);
        // ffn1 (wide tiles)
        tgemm_wide<<<dim3(2 * HH / 128, NN / 64), 128>>>(outb, ffn_w1, ffn_w1, BIG, ffn_b1, nullptr,
                                                         ffn, NN, 2 * HH, HH, 1, 0);
        tgemm<<<dim3(HH / 64, NN / 64), 128>>>(ffn, ffn_w2, ffn_w2, BIG, ffn_b2, nullptr,
                                               outb, 1.f, h, NN, HH, 2 * HH, 1, 0);
    }

    // head
    tgemm<<<dim3(HH / 64, NN / 64), 128>>>(h, mlp_w1, mlp_w1, BIG, mlp_b1, nullptr,
                                           nullptr, 0.f, hid, NN, HH, HH, 1, 0);
    mlp2_sym<<<dim3(NN / 64, NN / 64), 128, sym_smem>>>(hid, mlp_w2, mlp_b2, (float*)d_out);
}